// round 2
// baseline (speedup 1.0000x reference)
#include <cuda_runtime.h>
#include <math.h>

#define NTOK  65536      // 16 * 4096 tokens
#define DIN   512
#define DK    256
#define MS    64

// 64 MB scratch for encoded activations (static __device__ array: allowed)
__device__ float g_encoded[(size_t)NTOK * DK];

// ---------------- packed f32x2 helpers ----------------
__device__ __forceinline__ unsigned long long pack2(float lo, float hi) {
    unsigned long long r;
    asm("mov.b64 %0, {%1, %2};" : "=l"(r) : "f"(lo), "f"(hi));
    return r;
}
__device__ __forceinline__ void unpack2(unsigned long long v, float& lo, float& hi) {
    asm("mov.b64 {%0, %1}, %2;" : "=f"(lo), "=f"(hi) : "l"(v));
}
__device__ __forceinline__ void ffma2(unsigned long long& d, unsigned long long a,
                                      unsigned long long b) {
    asm("fma.rn.f32x2 %0, %1, %2, %3;" : "=l"(d) : "l"(a), "l"(b), "l"(d));
}

// ---------------------------------------------------------------------------
// C[row, :] = act(A[row, :] . W[col, :] + bias[col])      (NT GEMM, K-major both)
// BM=128, BN=64, BK=16, 256 threads, per-thread 8x4 via 4x f32x2 row-pairs.
// ---------------------------------------------------------------------------
template<int KDIM, bool DO_TANH>
__global__ void __launch_bounds__(256)
gemm_nt(const float* __restrict__ A, const float* __restrict__ W,
        const float* __restrict__ bias, float* __restrict__ C, int ldc)
{
    const int BM = 128, BN = 64, BK = 16;
    __shared__ float As[BK][BM];
    __shared__ float Ws[BK][BN];

    const int tid = threadIdx.x;
    const int tm = tid >> 4;   // 0..15 -> rows tm*8 .. tm*8+7
    const int tn = tid & 15;   // 0..15 -> cols tn*4 .. tn*4+3

    const float* Ap = A + (size_t)blockIdx.x * BM * KDIM;
    const float* Wp = W + (size_t)blockIdx.y * BN * KDIM;

    unsigned long long acc[4][4];
#pragma unroll
    for (int i = 0; i < 4; i++)
#pragma unroll
        for (int j = 0; j < 4; j++) acc[i][j] = 0ull;

    for (int k0 = 0; k0 < KDIM; k0 += BK) {
        // load A tile: 128x16 = 512 float4, 2 per thread (transpose on store)
#pragma unroll
        for (int l = 0; l < 2; l++) {
            int f   = tid + l * 256;
            int row = f >> 2;
            int kq  = (f & 3) << 2;
            float4 v = *(const float4*)(Ap + (size_t)row * KDIM + k0 + kq);
            As[kq + 0][row] = v.x; As[kq + 1][row] = v.y;
            As[kq + 2][row] = v.z; As[kq + 3][row] = v.w;
        }
        // load W tile: 64x16 = 256 float4, 1 per thread
        {
            int row = tid >> 2;
            int kq  = (tid & 3) << 2;
            float4 v = *(const float4*)(Wp + (size_t)row * KDIM + k0 + kq);
            Ws[kq + 0][row] = v.x; Ws[kq + 1][row] = v.y;
            Ws[kq + 2][row] = v.z; Ws[kq + 3][row] = v.w;
        }
        __syncthreads();

#pragma unroll
        for (int kk = 0; kk < BK; kk++) {
            const unsigned long long* ap =
                (const unsigned long long*)&As[kk][tm * 8];
            unsigned long long av[4];
            av[0] = ap[0]; av[1] = ap[1]; av[2] = ap[2]; av[3] = ap[3];
            float4 wv = *(const float4*)&Ws[kk][tn * 4];
            unsigned long long w2[4];
            w2[0] = pack2(wv.x, wv.x); w2[1] = pack2(wv.y, wv.y);
            w2[2] = pack2(wv.z, wv.z); w2[3] = pack2(wv.w, wv.w);
#pragma unroll
            for (int i = 0; i < 4; i++)
#pragma unroll
                for (int j = 0; j < 4; j++)
                    ffma2(acc[i][j], av[i], w2[j]);
        }
        __syncthreads();
    }

    // epilogue
    const int col  = blockIdx.y * BN + tn * 4;
    const int row0 = blockIdx.x * BM + tm * 8;
    float4 b4 = *(const float4*)(bias + col);
#pragma unroll
    for (int i = 0; i < 4; i++) {
        float lo[4], hi[4];
#pragma unroll
        for (int j = 0; j < 4; j++) unpack2(acc[i][j], lo[j], hi[j]);
        float4 o0, o1;
        o0.x = lo[0] + b4.x; o0.y = lo[1] + b4.y;
        o0.z = lo[2] + b4.z; o0.w = lo[3] + b4.w;
        o1.x = hi[0] + b4.x; o1.y = hi[1] + b4.y;
        o1.z = hi[2] + b4.z; o1.w = hi[3] + b4.w;
        if (DO_TANH) {
            o0.x = tanhf(o0.x); o0.y = tanhf(o0.y);
            o0.z = tanhf(o0.z); o0.w = tanhf(o0.w);
            o1.x = tanhf(o1.x); o1.y = tanhf(o1.y);
            o1.z = tanhf(o1.z); o1.w = tanhf(o1.w);
        }
        *(float4*)(C + (size_t)(row0 + 2 * i)     * ldc + col) = o0;
        *(float4*)(C + (size_t)(row0 + 2 * i + 1) * ldc + col) = o1;
    }
}

// ---------------------------------------------------------------------------
// Attention: 64 tokens per block, 256 threads.
//   logits[t,s] = encoded[t,:] . mem[s,:] / 16 ; softmax over s (64 slots)
//   memory[t,:] = attn[t,:] @ mem
// smem: Es[64][260] + Ms[64][260] + Ls[64][65]  = 149760 B (dynamic)
// ---------------------------------------------------------------------------
#define RS 260                     // row stride (260/4 = 65, odd -> conflict-free)
#define ATTN_SMEM ((2 * 64 * RS + 64 * 65) * (int)sizeof(float))

__global__ void __launch_bounds__(256)
attn_kernel(const float* __restrict__ mem, float* __restrict__ att_out,
            float* __restrict__ mem_out)
{
    extern __shared__ float sm[];
    float* Es = sm;                    // [64][RS]
    float* Ms = sm + 64 * RS;          // [64][RS]
    float* Ls = sm + 2 * 64 * RS;      // [64 slots][65]  slot-major

    const int tid = threadIdx.x;
    const int t0  = blockIdx.x * 64;

    // ---- load encoded tile + memory bank (coalesced float4) ----
    for (int f = tid; f < 64 * 64; f += 256) {
        int row = f >> 6;
        int col = (f & 63) << 2;
        *(float4*)&Es[row * RS + col] =
            *(const float4*)(g_encoded + (size_t)(t0 + row) * DK + col);
        *(float4*)&Ms[row * RS + col] =
            *(const float4*)(mem + (size_t)row * DK + col);
    }
    __syncthreads();

    // ---- logits: thread handles token t = tid%64, slots sg*16..sg*16+15 ----
    {
        const int t  = tid & 63;
        const int sg = (tid >> 6) << 4;          // 0,16,32,48
        float acc[16];
#pragma unroll
        for (int s = 0; s < 16; s++) acc[s] = 0.0f;
        for (int k = 0; k < DK; k += 4) {
            float4 e4 = *(const float4*)&Es[t * RS + k];
#pragma unroll
            for (int s = 0; s < 16; s++) {
                float4 m4 = *(const float4*)&Ms[(sg + s) * RS + k];
                acc[s] += e4.x * m4.x + e4.y * m4.y + e4.z * m4.z + e4.w * m4.w;
            }
        }
#pragma unroll
        for (int s = 0; s < 16; s++)
            Ls[(sg + s) * 65 + t] = acc[s] * 0.0625f;   // / sqrt(256)
    }
    __syncthreads();

    // ---- softmax over 64 slots: warp w handles tokens w*8..w*8+7 ----
    {
        const int wid = tid >> 5, lane = tid & 31;
        for (int tt = 0; tt < 8; tt++) {
            int t = wid * 8 + tt;
            float v0 = Ls[lane * 65 + t];
            float v1 = Ls[(lane + 32) * 65 + t];
            float mx = fmaxf(v0, v1);
#pragma unroll
            for (int o = 16; o; o >>= 1)
                mx = fmaxf(mx, __shfl_xor_sync(0xffffffffu, mx, o));
            float e0 = expf(v0 - mx), e1 = expf(v1 - mx);
            float s = e0 + e1;
#pragma unroll
            for (int o = 16; o; o >>= 1)
                s += __shfl_xor_sync(0xffffffffu, s, o);
            float inv = 1.0f / s;
            e0 *= inv; e1 *= inv;
            Ls[lane * 65 + t]        = e0;   // in-place: Ls now holds attention
            Ls[(lane + 32) * 65 + t] = e1;
            att_out[(size_t)(t0 + t) * MS + lane]      = e0;
            att_out[(size_t)(t0 + t) * MS + lane + 32] = e1;
        }
    }
    __syncthreads();

    // ---- weighted read: thread handles token t, k-range kc..kc+63 ----
    {
        const int t  = tid & 63;
        const int kc = (tid >> 6) << 6;          // 0,64,128,192
        float acc[64];
#pragma unroll
        for (int j = 0; j < 64; j++) acc[j] = 0.0f;
#pragma unroll 4
        for (int s = 0; s < MS; s++) {
            float a = Ls[s * 65 + t];
            const float4* mp = (const float4*)&Ms[s * RS + kc];
#pragma unroll
            for (int j = 0; j < 16; j++) {
                float4 m4 = mp[j];
                acc[4 * j + 0] += a * m4.x;
                acc[4 * j + 1] += a * m4.y;
                acc[4 * j + 2] += a * m4.z;
                acc[4 * j + 3] += a * m4.w;
            }
        }
        float* outp = mem_out + (size_t)(t0 + t) * DK + kc;
#pragma unroll
        for (int j = 0; j < 16; j++) {
            float4 o;
            o.x = acc[4 * j + 0]; o.y = acc[4 * j + 1];
            o.z = acc[4 * j + 2]; o.w = acc[4 * j + 3];
            *(float4*)(outp + 4 * j) = o;
        }
    }
}

// ---------------------------------------------------------------------------
extern "C" void kernel_launch(void* const* d_in, const int* in_sizes, int n_in,
                              void* d_out, int out_size)
{
    const float* seq   = (const float*)d_in[0];   // [16,4096,512]
    const float* enc_w = (const float*)d_in[1];   // [256,512]
    const float* enc_b = (const float*)d_in[2];   // [256]
    const float* mem   = (const float*)d_in[3];   // [64,256]
    const float* dec_w = (const float*)d_in[4];   // [512,256]
    const float* dec_b = (const float*)d_in[5];   // [512]

    float* recon = (float*)d_out;                        // [NTOK,512]
    float* att   = recon + (size_t)NTOK * DIN;           // [NTOK,64]
    float* memo  = att   + (size_t)NTOK * MS;            // [NTOK,256]

    float* enc_out = nullptr;
    cudaGetSymbolAddress((void**)&enc_out, g_encoded);

    cudaFuncSetAttribute(attn_kernel,
                         cudaFuncAttributeMaxDynamicSharedMemorySize, ATTN_SMEM);

    // 1) encode GEMM + tanh -> g_encoded
    dim3 g1(NTOK / 128, DK / 64);
    gemm_nt<DIN, true><<<g1, 256>>>(seq, enc_w, enc_b, enc_out, DK);

    // 2) attention + read -> att, memo
    attn_kernel<<<NTOK / 64, 256, ATTN_SMEM>>>(mem, att, memo);

    // 3) decode GEMM + bias -> recon
    dim3 g3(NTOK / 128, DIN / 64);
    gemm_nt<DK, false><<<g3, 256>>>(memo, dec_w, dec_b, recon, DIN);
}

// round 4
// speedup vs baseline: 1.6950x; 1.6950x over previous
#include <cuda_runtime.h>
#include <cuda_bf16.h>
#include <cstdint>
#include <math.h>

#define NTOK  65536
#define DIN   512
#define DK    256
#define MS    64

__device__ float g_encoded[(size_t)NTOK * DK];

// ======================= helpers =======================
__device__ __forceinline__ uint32_t smem_u32(const void* p) {
    uint32_t a;
    asm("{ .reg .u64 t; cvta.to.shared.u64 t, %1; cvt.u32.u64 %0, t; }"
        : "=r"(a) : "l"(p));
    return a;
}
__device__ __forceinline__ uint32_t pack_bf2(float a, float b) {
    __nv_bfloat162 t = __floats2bfloat162_rn(a, b);
    return *reinterpret_cast<uint32_t*>(&t);
}
__device__ __forceinline__ void split4(float4 v, unsigned long long& hi,
                                       unsigned long long& lo) {
    float r0 = v.x - __bfloat162float(__float2bfloat16_rn(v.x));
    float r1 = v.y - __bfloat162float(__float2bfloat16_rn(v.y));
    float r2 = v.z - __bfloat162float(__float2bfloat16_rn(v.z));
    float r3 = v.w - __bfloat162float(__float2bfloat16_rn(v.w));
    hi = (unsigned long long)pack_bf2(v.x, v.y) |
         ((unsigned long long)pack_bf2(v.z, v.w) << 32);
    lo = (unsigned long long)pack_bf2(r0, r1) |
         ((unsigned long long)pack_bf2(r2, r3) << 32);
}
__device__ __forceinline__ void sts64(uint32_t addr, unsigned long long v) {
    asm volatile("st.shared.b64 [%0], %1;" :: "r"(addr), "l"(v) : "memory");
}
__device__ __forceinline__ void ldsm_x4(uint32_t& r0, uint32_t& r1,
                                        uint32_t& r2, uint32_t& r3, uint32_t addr) {
    asm volatile("ldmatrix.sync.aligned.m8n8.x4.shared.b16 {%0,%1,%2,%3}, [%4];"
                 : "=r"(r0), "=r"(r1), "=r"(r2), "=r"(r3) : "r"(addr));
}
__device__ __forceinline__ void mma16816(float* d, const uint32_t* a,
                                         uint32_t b0, uint32_t b1) {
    asm volatile(
        "mma.sync.aligned.m16n8k16.row.col.f32.bf16.bf16.f32 "
        "{%0,%1,%2,%3}, {%4,%5,%6,%7}, {%8,%9}, {%0,%1,%2,%3};"
        : "+f"(d[0]), "+f"(d[1]), "+f"(d[2]), "+f"(d[3])
        : "r"(a[0]), "r"(a[1]), "r"(a[2]), "r"(a[3]), "r"(b0), "r"(b1));
}

// ===========================================================================
// HMMA GEMM: C[M,nout] = A[M,KDIM] @ W[nout,KDIM]^T + bias (opt tanh)
// BM=128, BN=128, BK=32, 256 threads. bf16 3-way split, f32 accum.
// smem per buffer: Ahi|Alo|Whi|Wlo, each 128 rows x 40 bf16 (80B stride).
// ===========================================================================
#define RSB   80            // row stride bytes (40 bf16)
#define PART  (128 * RSB)   // 10240 B
#define BUFSZ (4 * PART)    // 40960 B
#define GEMM_SMEM (2 * BUFSZ)

template<int KDIM, bool DO_TANH>
__global__ void __launch_bounds__(256, 1)
hmma_gemm(const float* __restrict__ A, const float* __restrict__ W,
          const float* __restrict__ bias, float* __restrict__ C, int nout)
{
    extern __shared__ char smc[];
    const uint32_t sb = smem_u32(smc);
    const int tid = threadIdx.x, wid = tid >> 5, lane = tid & 31;
    const int wm = wid & 3, wn = wid >> 2;       // warp 32-row x 64-col tile
    const int NCH = KDIM / 32;

    const size_t arow0 = (size_t)blockIdx.x * 128;
    const int n0 = blockIdx.y * 128;
    const float* Ap = A + arow0 * KDIM;
    const float* Wp = W + (size_t)n0 * KDIM;

    // per-thread gmem mapping: 4 float4 for A, 4 for W per chunk
    const int lrow = tid >> 3;          // 0..31 (x4 iters -> 128 rows)
    const int lc4  = tid & 7;           // 0..7  (col quad within 32)

    float acc[2][8][4];
#pragma unroll
    for (int i = 0; i < 2; i++)
#pragma unroll
        for (int j = 0; j < 8; j++)
#pragma unroll
            for (int k = 0; k < 4; k++) acc[i][j][k] = 0.0f;

    float4 av[4], wv[4];

    auto load_chunk = [&](int c) {
        const int k0 = c * 32;
#pragma unroll
        for (int it = 0; it < 4; it++) {
            int row = lrow + it * 32;
            av[it] = __ldg((const float4*)(Ap + (size_t)row * KDIM + k0 + lc4 * 4));
            wv[it] = __ldg((const float4*)(Wp + (size_t)row * KDIM + k0 + lc4 * 4));
        }
    };
    auto store_chunk = [&](int buf) {
        const uint32_t base = sb + buf * BUFSZ;
#pragma unroll
        for (int it = 0; it < 4; it++) {
            int row = lrow + it * 32;
            uint32_t off = row * RSB + lc4 * 8;
            unsigned long long hi, lo;
            split4(av[it], hi, lo);
            sts64(base + off, hi);
            sts64(base + PART + off, lo);
            split4(wv[it], hi, lo);
            sts64(base + 2 * PART + off, hi);
            sts64(base + 3 * PART + off, lo);
        }
    };
    auto compute = [&](int buf) {
        const uint32_t base = sb + buf * BUFSZ;
        const uint32_t lr = lane & 15, lh = (lane >> 4) * 16;
#pragma unroll
        for (int ks = 0; ks < 2; ks++) {
            uint32_t ahi[2][4], alo[2][4], whi[4][4], wlo[4][4];
#pragma unroll
            for (int mt = 0; mt < 2; mt++) {
                uint32_t ao = (wm * 32 + mt * 16 + lr) * RSB + ks * 32 + lh;
                ldsm_x4(ahi[mt][0], ahi[mt][1], ahi[mt][2], ahi[mt][3], base + ao);
                ldsm_x4(alo[mt][0], alo[mt][1], alo[mt][2], alo[mt][3],
                        base + PART + ao);
            }
#pragma unroll
            for (int g = 0; g < 4; g++) {
                uint32_t wo = (wn * 64 + g * 16 + lr) * RSB + ks * 32 + lh;
                ldsm_x4(whi[g][0], whi[g][1], whi[g][2], whi[g][3],
                        base + 2 * PART + wo);
                ldsm_x4(wlo[g][0], wlo[g][1], wlo[g][2], wlo[g][3],
                        base + 3 * PART + wo);
            }
#pragma unroll
            for (int mt = 0; mt < 2; mt++)
#pragma unroll
                for (int g = 0; g < 4; g++) {
                    // hi x hi
                    mma16816(acc[mt][2 * g],     ahi[mt], whi[g][0], whi[g][2]);
                    mma16816(acc[mt][2 * g + 1], ahi[mt], whi[g][1], whi[g][3]);
                    // hi x lo
                    mma16816(acc[mt][2 * g],     ahi[mt], wlo[g][0], wlo[g][2]);
                    mma16816(acc[mt][2 * g + 1], ahi[mt], wlo[g][1], wlo[g][3]);
                    // lo x hi
                    mma16816(acc[mt][2 * g],     alo[mt], whi[g][0], whi[g][2]);
                    mma16816(acc[mt][2 * g + 1], alo[mt], whi[g][1], whi[g][3]);
                }
        }
    };

    load_chunk(0);
    store_chunk(0);
    __syncthreads();
    for (int c = 0; c < NCH; c++) {
        if (c + 1 < NCH) load_chunk(c + 1);
        compute(c & 1);
        __syncthreads();
        if (c + 1 < NCH) {
            store_chunk((c + 1) & 1);
            __syncthreads();
        }
    }

    // epilogue
    const int tq = lane >> 2, tr = lane & 3;
#pragma unroll
    for (int mt = 0; mt < 2; mt++) {
        size_t r0 = arow0 + wm * 32 + mt * 16 + tq;
#pragma unroll
        for (int nt = 0; nt < 8; nt++) {
            int gn = n0 + wn * 64 + nt * 8 + tr * 2;
            float bx = bias[gn], by = bias[gn + 1];
            float2 o0, o1;
            o0.x = acc[mt][nt][0] + bx; o0.y = acc[mt][nt][1] + by;
            o1.x = acc[mt][nt][2] + bx; o1.y = acc[mt][nt][3] + by;
            if (DO_TANH) {
                o0.x = tanhf(o0.x); o0.y = tanhf(o0.y);
                o1.x = tanhf(o1.x); o1.y = tanhf(o1.y);
            }
            *(float2*)(C + r0 * nout + gn)       = o0;
            *(float2*)(C + (r0 + 8) * nout + gn) = o1;
        }
    }
}

// ---------------------------------------------------------------------------
// Attention (unchanged): 64 tokens/block, 256 threads.
// ---------------------------------------------------------------------------
#define RS 260
#define ATTN_SMEM ((2 * 64 * RS + 64 * 65) * (int)sizeof(float))

__global__ void __launch_bounds__(256)
attn_kernel(const float* __restrict__ mem, float* __restrict__ att_out,
            float* __restrict__ mem_out)
{
    extern __shared__ float sm[];
    float* Es = sm;
    float* Ms = sm + 64 * RS;
    float* Ls = sm + 2 * 64 * RS;

    const int tid = threadIdx.x;
    const int t0  = blockIdx.x * 64;

    for (int f = tid; f < 64 * 64; f += 256) {
        int row = f >> 6;
        int col = (f & 63) << 2;
        *(float4*)&Es[row * RS + col] =
            *(const float4*)(g_encoded + (size_t)(t0 + row) * DK + col);
        *(float4*)&Ms[row * RS + col] =
            *(const float4*)(mem + (size_t)row * DK + col);
    }
    __syncthreads();

    {
        const int t  = tid & 63;
        const int sg = (tid >> 6) << 4;
        float acc[16];
#pragma unroll
        for (int s = 0; s < 16; s++) acc[s] = 0.0f;
        for (int k = 0; k < DK; k += 4) {
            float4 e4 = *(const float4*)&Es[t * RS + k];
#pragma unroll
            for (int s = 0; s < 16; s++) {
                float4 m4 = *(const float4*)&Ms[(sg + s) * RS + k];
                acc[s] += e4.x * m4.x + e4.y * m4.y + e4.z * m4.z + e4.w * m4.w;
            }
        }
#pragma unroll
        for (int s = 0; s < 16; s++)
            Ls[(sg + s) * 65 + t] = acc[s] * 0.0625f;
    }
    __syncthreads();

    {
        const int wid = tid >> 5, lane = tid & 31;
        for (int tt = 0; tt < 8; tt++) {
            int t = wid * 8 + tt;
            float v0 = Ls[lane * 65 + t];
            float v1 = Ls[(lane + 32) * 65 + t];
            float mx = fmaxf(v0, v1);
#pragma unroll
            for (int o = 16; o; o >>= 1)
                mx = fmaxf(mx, __shfl_xor_sync(0xffffffffu, mx, o));
            float e0 = expf(v0 - mx), e1 = expf(v1 - mx);
            float s = e0 + e1;
#pragma unroll
            for (int o = 16; o; o >>= 1)
                s += __shfl_xor_sync(0xffffffffu, s, o);
            float inv = 1.0f / s;
            e0 *= inv; e1 *= inv;
            Ls[lane * 65 + t]        = e0;
            Ls[(lane + 32) * 65 + t] = e1;
            att_out[(size_t)(t0 + t) * MS + lane]      = e0;
            att_out[(size_t)(t0 + t) * MS + lane + 32] = e1;
        }
    }
    __syncthreads();

    {
        const int t  = tid & 63;
        const int kc = (tid >> 6) << 6;
        float acc[64];
#pragma unroll
        for (int j = 0; j < 64; j++) acc[j] = 0.0f;
#pragma unroll 4
        for (int s = 0; s < MS; s++) {
            float a = Ls[s * 65 + t];
            const float4* mp = (const float4*)&Ms[s * RS + kc];
#pragma unroll
            for (int j = 0; j < 16; j++) {
                float4 m4 = mp[j];
                acc[4 * j + 0] += a * m4.x;
                acc[4 * j + 1] += a * m4.y;
                acc[4 * j + 2] += a * m4.z;
                acc[4 * j + 3] += a * m4.w;
            }
        }
        float* outp = mem_out + (size_t)(t0 + t) * DK + kc;
#pragma unroll
        for (int j = 0; j < 16; j++) {
            float4 o;
            o.x = acc[4 * j + 0]; o.y = acc[4 * j + 1];
            o.z = acc[4 * j + 2]; o.w = acc[4 * j + 3];
            *(float4*)(outp + 4 * j) = o;
        }
    }
}

// ---------------------------------------------------------------------------
extern "C" void kernel_launch(void* const* d_in, const int* in_sizes, int n_in,
                              void* d_out, int out_size)
{
    const float* seq   = (const float*)d_in[0];
    const float* enc_w = (const float*)d_in[1];
    const float* enc_b = (const float*)d_in[2];
    const float* mem   = (const float*)d_in[3];
    const float* dec_w = (const float*)d_in[4];
    const float* dec_b = (const float*)d_in[5];

    float* recon = (float*)d_out;
    float* att   = recon + (size_t)NTOK * DIN;
    float* memo  = att   + (size_t)NTOK * MS;

    float* enc_out = nullptr;
    cudaGetSymbolAddress((void**)&enc_out, g_encoded);

    cudaFuncSetAttribute(hmma_gemm<DIN, true>,
                         cudaFuncAttributeMaxDynamicSharedMemorySize, GEMM_SMEM);
    cudaFuncSetAttribute(hmma_gemm<DK, false>,
                         cudaFuncAttributeMaxDynamicSharedMemorySize, GEMM_SMEM);
    cudaFuncSetAttribute(attn_kernel,
                         cudaFuncAttributeMaxDynamicSharedMemorySize, ATTN_SMEM);

    // 1) encode: [65536,512] @ [256,512]^T + bias, tanh -> g_encoded
    dim3 g1(NTOK / 128, DK / 128);
    hmma_gemm<DIN, true><<<g1, 256, GEMM_SMEM>>>(seq, enc_w, enc_b, enc_out, DK);

    // 2) attention + weighted read
    attn_kernel<<<NTOK / 64, 256, ATTN_SMEM>>>(mem, att, memo);

    // 3) decode: [65536,256] @ [512,256]^T + bias
    dim3 g3(NTOK / 128, DIN / 128);
    hmma_gemm<DK, false><<<g3, 256, GEMM_SMEM>>>(memo, dec_w, dec_b, recon, DIN);
}

// round 5
// speedup vs baseline: 2.1299x; 1.2566x over previous
#include <cuda_runtime.h>
#include <cuda_bf16.h>
#include <cstdint>
#include <math.h>

#define NTOK  65536
#define DIN   512
#define DK    256
#define MS    64

// ---------------- static scratch (bf16 hi/lo splits) ----------------
__device__ __nv_bfloat16 g_encw_hi[DK * DIN], g_encw_lo[DK * DIN];
__device__ __nv_bfloat16 g_decw_hi[DIN * DK], g_decw_lo[DIN * DK];
__device__ __nv_bfloat16 g_mem_hi[MS * DK],  g_mem_lo[MS * DK];
__device__ __nv_bfloat16 g_enc_hi[(size_t)NTOK * DK], g_enc_lo[(size_t)NTOK * DK];
__device__ __nv_bfloat16 g_memo_hi[(size_t)NTOK * DK], g_memo_lo[(size_t)NTOK * DK];

// ======================= helpers =======================
__device__ __forceinline__ uint32_t smem_u32(const void* p) {
    uint32_t a;
    asm("{ .reg .u64 t; cvta.to.shared.u64 t, %1; cvt.u32.u64 %0, t; }"
        : "=r"(a) : "l"(p));
    return a;
}
__device__ __forceinline__ uint32_t pack_bf2(float a, float b) {
    __nv_bfloat162 t = __floats2bfloat162_rn(a, b);
    return *reinterpret_cast<uint32_t*>(&t);
}
__device__ __forceinline__ void split2(float a, float b, uint32_t& hi, uint32_t& lo) {
    __nv_bfloat16 ha = __float2bfloat16_rn(a), hb = __float2bfloat16_rn(b);
    __nv_bfloat162 hp; hp.x = ha; hp.y = hb;
    hi = *reinterpret_cast<uint32_t*>(&hp);
    lo = pack_bf2(a - __bfloat162float(ha), b - __bfloat162float(hb));
}
__device__ __forceinline__ void split4(float4 v, unsigned long long& hi,
                                       unsigned long long& lo) {
    uint32_t h0, l0, h1, l1;
    split2(v.x, v.y, h0, l0);
    split2(v.z, v.w, h1, l1);
    hi = (unsigned long long)h0 | ((unsigned long long)h1 << 32);
    lo = (unsigned long long)l0 | ((unsigned long long)l1 << 32);
}
__device__ __forceinline__ void sts64(uint32_t addr, unsigned long long v) {
    asm volatile("st.shared.b64 [%0], %1;" :: "r"(addr), "l"(v) : "memory");
}
__device__ __forceinline__ void sts128(uint32_t addr, uint4 v) {
    asm volatile("st.shared.v4.b32 [%0], {%1,%2,%3,%4};"
                 :: "r"(addr), "r"(v.x), "r"(v.y), "r"(v.z), "r"(v.w) : "memory");
}
__device__ __forceinline__ void ldsm_x4(uint32_t* r, uint32_t addr) {
    asm volatile("ldmatrix.sync.aligned.m8n8.x4.shared.b16 {%0,%1,%2,%3}, [%4];"
                 : "=r"(r[0]), "=r"(r[1]), "=r"(r[2]), "=r"(r[3]) : "r"(addr));
}
__device__ __forceinline__ void ldsm_x4_t(uint32_t* r, uint32_t addr) {
    asm volatile("ldmatrix.sync.aligned.m8n8.x4.trans.shared.b16 {%0,%1,%2,%3}, [%4];"
                 : "=r"(r[0]), "=r"(r[1]), "=r"(r[2]), "=r"(r[3]) : "r"(addr));
}
__device__ __forceinline__ void mma16816(float* d, const uint32_t* a,
                                         uint32_t b0, uint32_t b1) {
    asm volatile(
        "mma.sync.aligned.m16n8k16.row.col.f32.bf16.bf16.f32 "
        "{%0,%1,%2,%3}, {%4,%5,%6,%7}, {%8,%9}, {%0,%1,%2,%3};"
        : "+f"(d[0]), "+f"(d[1]), "+f"(d[2]), "+f"(d[3])
        : "r"(a[0]), "r"(a[1]), "r"(a[2]), "r"(a[3]), "r"(b0), "r"(b1));
}

// ---------------- prep: split static tensors to bf16 hi/lo ----------------
__global__ void prep_split(const float* __restrict__ ew, const float* __restrict__ dw,
                           const float* __restrict__ mm)
{
    int i = blockIdx.x * blockDim.x + threadIdx.x;
    int st = gridDim.x * blockDim.x;
    for (int j = i; j < DK * DIN; j += st) {
        float v = ew[j];
        __nv_bfloat16 h = __float2bfloat16_rn(v);
        g_encw_hi[j] = h;
        g_encw_lo[j] = __float2bfloat16_rn(v - __bfloat162float(h));
    }
    for (int j = i; j < DIN * DK; j += st) {
        float v = dw[j];
        __nv_bfloat16 h = __float2bfloat16_rn(v);
        g_decw_hi[j] = h;
        g_decw_lo[j] = __float2bfloat16_rn(v - __bfloat162float(h));
    }
    for (int j = i; j < MS * DK; j += st) {
        float v = mm[j];
        __nv_bfloat16 h = __float2bfloat16_rn(v);
        g_mem_hi[j] = h;
        g_mem_lo[j] = __float2bfloat16_rn(v - __bfloat162float(h));
    }
}

// ===========================================================================
// HMMA GEMM. MODE 0 (encode): A fp32 split in-kernel, W pre-split,
//   epilogue tanh -> bf16 hi/lo outputs. MODE 1 (decode): A pre-split bf16,
//   W pre-split, epilogue fp32 C.
// BM=128, BN=128, BK=32. grid.x = N tiles (fast), grid.y = M tiles.
// ===========================================================================
#define RSB   80
#define PART  (128 * RSB)
#define BUFSZ (4 * PART)
#define GEMM_SMEM (2 * BUFSZ)

template<int KDIM, int MODE>
__global__ void __launch_bounds__(256, 1)
hmma_gemm2(const float* __restrict__ A32,
           const __nv_bfloat16* __restrict__ Ahi, const __nv_bfloat16* __restrict__ Alo,
           const __nv_bfloat16* __restrict__ Whi, const __nv_bfloat16* __restrict__ Wlo,
           const float* __restrict__ bias,
           float* __restrict__ C,
           __nv_bfloat16* __restrict__ Ohi, __nv_bfloat16* __restrict__ Olo,
           int nout)
{
    extern __shared__ char smc[];
    const uint32_t sb = smem_u32(smc);
    const int tid = threadIdx.x, wid = tid >> 5, lane = tid & 31;
    const int wm = wid & 3, wn = wid >> 2;
    const int NCH = KDIM / 32;

    const size_t arow0 = (size_t)blockIdx.y * 128;
    const int n0 = blockIdx.x * 128;

    // mapping for fp32 A loads (MODE 0)
    const int lrow = tid >> 3, lc4 = tid & 7;
    // mapping for bf16 loads (uint4 = 8 bf16)
    const int brow0 = tid >> 2, bc8 = tid & 3;

    float acc[2][8][4];
#pragma unroll
    for (int i = 0; i < 2; i++)
#pragma unroll
        for (int j = 0; j < 8; j++)
#pragma unroll
            for (int k = 0; k < 4; k++) acc[i][j][k] = 0.0f;

    float4 av[4];
    uint4 ah4[2], al4[2], wh4[2], wl4[2];

    auto load_chunk = [&](int c) {
        const int k0 = c * 32;
        if (MODE == 0) {
#pragma unroll
            for (int it = 0; it < 4; it++) {
                int row = lrow + it * 32;
                av[it] = __ldg((const float4*)(A32 + (arow0 + row) * KDIM + k0 + lc4 * 4));
            }
        } else {
#pragma unroll
            for (int l = 0; l < 2; l++) {
                int row = brow0 + l * 64;
                ah4[l] = __ldg((const uint4*)(Ahi + (arow0 + row) * KDIM + k0) + bc8);
                al4[l] = __ldg((const uint4*)(Alo + (arow0 + row) * KDIM + k0) + bc8);
            }
        }
#pragma unroll
        for (int l = 0; l < 2; l++) {
            int row = brow0 + l * 64;
            wh4[l] = __ldg((const uint4*)(Whi + (size_t)(n0 + row) * KDIM + k0) + bc8);
            wl4[l] = __ldg((const uint4*)(Wlo + (size_t)(n0 + row) * KDIM + k0) + bc8);
        }
    };
    auto store_chunk = [&](int buf) {
        const uint32_t base = sb + buf * BUFSZ;
        if (MODE == 0) {
#pragma unroll
            for (int it = 0; it < 4; it++) {
                int row = lrow + it * 32;
                uint32_t off = row * RSB + lc4 * 8;
                unsigned long long hi, lo;
                split4(av[it], hi, lo);
                sts64(base + off, hi);
                sts64(base + PART + off, lo);
            }
        } else {
#pragma unroll
            for (int l = 0; l < 2; l++) {
                int row = brow0 + l * 64;
                uint32_t off = row * RSB + bc8 * 16;
                sts128(base + off, ah4[l]);
                sts128(base + PART + off, al4[l]);
            }
        }
#pragma unroll
        for (int l = 0; l < 2; l++) {
            int row = brow0 + l * 64;
            uint32_t off = row * RSB + bc8 * 16;
            sts128(base + 2 * PART + off, wh4[l]);
            sts128(base + 3 * PART + off, wl4[l]);
        }
    };
    auto compute = [&](int buf) {
        const uint32_t base = sb + buf * BUFSZ;
        const uint32_t lr = lane & 15, lh = (lane >> 4) * 16;
#pragma unroll
        for (int ks = 0; ks < 2; ks++) {
            uint32_t ahf[2][4], alf[2][4], whf[4][4], wlf[4][4];
#pragma unroll
            for (int mt = 0; mt < 2; mt++) {
                uint32_t ao = (wm * 32 + mt * 16 + lr) * RSB + ks * 32 + lh;
                ldsm_x4(ahf[mt], base + ao);
                ldsm_x4(alf[mt], base + PART + ao);
            }
#pragma unroll
            for (int g = 0; g < 4; g++) {
                uint32_t wo = (wn * 64 + g * 16 + lr) * RSB + ks * 32 + lh;
                ldsm_x4(whf[g], base + 2 * PART + wo);
                ldsm_x4(wlf[g], base + 3 * PART + wo);
            }
#pragma unroll
            for (int mt = 0; mt < 2; mt++)
#pragma unroll
                for (int g = 0; g < 4; g++) {
                    mma16816(acc[mt][2 * g],     ahf[mt], whf[g][0], whf[g][2]);
                    mma16816(acc[mt][2 * g + 1], ahf[mt], whf[g][1], whf[g][3]);
                    mma16816(acc[mt][2 * g],     ahf[mt], wlf[g][0], wlf[g][2]);
                    mma16816(acc[mt][2 * g + 1], ahf[mt], wlf[g][1], wlf[g][3]);
                    mma16816(acc[mt][2 * g],     alf[mt], whf[g][0], whf[g][2]);
                    mma16816(acc[mt][2 * g + 1], alf[mt], whf[g][1], whf[g][3]);
                }
        }
    };

    load_chunk(0);
    store_chunk(0);
    __syncthreads();
    for (int c = 0; c < NCH; c++) {
        if (c + 1 < NCH) load_chunk(c + 1);
        compute(c & 1);
        __syncthreads();
        if (c + 1 < NCH) {
            store_chunk((c + 1) & 1);
            __syncthreads();
        }
    }

    // epilogue
    const int tq = lane >> 2, tr = lane & 3;
#pragma unroll
    for (int mt = 0; mt < 2; mt++) {
        size_t r0 = arow0 + wm * 32 + mt * 16 + tq;
#pragma unroll
        for (int nt = 0; nt < 8; nt++) {
            int gn = n0 + wn * 64 + nt * 8 + tr * 2;
            float bx = bias[gn], by = bias[gn + 1];
            float v0 = acc[mt][nt][0] + bx, v1 = acc[mt][nt][1] + by;
            float v2 = acc[mt][nt][2] + bx, v3 = acc[mt][nt][3] + by;
            if (MODE == 0) {
                v0 = tanhf(v0); v1 = tanhf(v1); v2 = tanhf(v2); v3 = tanhf(v3);
                uint32_t h, l;
                split2(v0, v1, h, l);
                *(uint32_t*)(Ohi + r0 * nout + gn) = h;
                *(uint32_t*)(Olo + r0 * nout + gn) = l;
                split2(v2, v3, h, l);
                *(uint32_t*)(Ohi + (r0 + 8) * nout + gn) = h;
                *(uint32_t*)(Olo + (r0 + 8) * nout + gn) = l;
            } else {
                float2 o0, o1;
                o0.x = v0; o0.y = v1; o1.x = v2; o1.y = v3;
                *(float2*)(C + r0 * nout + gn)       = o0;
                *(float2*)(C + (r0 + 8) * nout + gn) = o1;
            }
        }
    }
}

// ===========================================================================
// Attention on HMMA: 128 tokens/block, 8 warps (each 16 tokens).
//   S = E @ mem^T (non-trans ldsm on mem), softmax in regs,
//   P repacked in-register to A-frags, memo = P @ mem (trans ldsm on mem).
// ===========================================================================
#define EROW 528   // 256 bf16 + 8 pad, bytes
#define AT_SMEM ((128 + 128 + 64 + 64) * EROW)   // 202752 B

__global__ void __launch_bounds__(256, 1)
attn_mma(float* __restrict__ att_out, float* __restrict__ mem_out)
{
    extern __shared__ char smc[];
    const uint32_t sb = smem_u32(smc);
    const uint32_t sEhi = sb, sElo = sb + 128 * EROW;
    const uint32_t sMhi = sb + 256 * EROW, sMlo = sMhi + 64 * EROW;

    const int tid = threadIdx.x, wid = tid >> 5, lane = tid & 31;
    const size_t t0 = (size_t)blockIdx.x * 128;

    // load E tile (bf16 hi/lo) and mem bank
#pragma unroll
    for (int it = 0; it < 16; it++) {
        int idx = tid + it * 256;
        int row = idx >> 5, c = idx & 31;
        uint4 vh = __ldg((const uint4*)(g_enc_hi + (t0 + row) * DK) + c);
        uint4 vl = __ldg((const uint4*)(g_enc_lo + (t0 + row) * DK) + c);
        sts128(sEhi + row * EROW + c * 16, vh);
        sts128(sElo + row * EROW + c * 16, vl);
    }
#pragma unroll
    for (int it = 0; it < 8; it++) {
        int idx = tid + it * 256;
        int row = idx >> 5, c = idx & 31;
        uint4 vh = __ldg((const uint4*)(g_mem_hi + row * DK) + c);
        uint4 vl = __ldg((const uint4*)(g_mem_lo + row * DK) + c);
        sts128(sMhi + row * EROW + c * 16, vh);
        sts128(sMlo + row * EROW + c * 16, vl);
    }
    __syncthreads();

    const int lr = lane & 15, half = lane >> 4;
    const int tq = lane >> 2, tr = lane & 3;
    const int r0 = wid * 16;

    // ---- logits S[128x64] ----
    float S[8][4];
#pragma unroll
    for (int i = 0; i < 8; i++)
#pragma unroll
        for (int j = 0; j < 4; j++) S[i][j] = 0.0f;

#pragma unroll
    for (int ks = 0; ks < 16; ks++) {
        uint32_t aoff = (r0 + lr) * EROW + ks * 32 + half * 16;
        uint32_t ahf[4], alf[4];
        ldsm_x4(ahf, sEhi + aoff);
        ldsm_x4(alf, sElo + aoff);
#pragma unroll
        for (int g = 0; g < 4; g++) {
            uint32_t woff = (g * 16 + lr) * EROW + ks * 32 + half * 16;
            uint32_t bh[4], bl[4];
            ldsm_x4(bh, sMhi + woff);
            ldsm_x4(bl, sMlo + woff);
            mma16816(S[2 * g],     ahf, bh[0], bh[2]);
            mma16816(S[2 * g + 1], ahf, bh[1], bh[3]);
            mma16816(S[2 * g],     ahf, bl[0], bl[2]);
            mma16816(S[2 * g + 1], ahf, bl[1], bl[3]);
            mma16816(S[2 * g],     alf, bh[0], bh[2]);
            mma16816(S[2 * g + 1], alf, bh[1], bh[3]);
        }
    }

    // ---- softmax over 64 slots (rows tq and tq+8) ----
    float m0 = -1e30f, m1 = -1e30f;
#pragma unroll
    for (int nt = 0; nt < 8; nt++) {
        m0 = fmaxf(m0, fmaxf(S[nt][0], S[nt][1]));
        m1 = fmaxf(m1, fmaxf(S[nt][2], S[nt][3]));
    }
    m0 = fmaxf(m0, __shfl_xor_sync(0xffffffffu, m0, 1));
    m0 = fmaxf(m0, __shfl_xor_sync(0xffffffffu, m0, 2));
    m1 = fmaxf(m1, __shfl_xor_sync(0xffffffffu, m1, 1));
    m1 = fmaxf(m1, __shfl_xor_sync(0xffffffffu, m1, 2));
    float s0 = 0.0f, s1 = 0.0f;
#pragma unroll
    for (int nt = 0; nt < 8; nt++) {
        S[nt][0] = expf((S[nt][0] - m0) * 0.0625f); s0 += S[nt][0];
        S[nt][1] = expf((S[nt][1] - m0) * 0.0625f); s0 += S[nt][1];
        S[nt][2] = expf((S[nt][2] - m1) * 0.0625f); s1 += S[nt][2];
        S[nt][3] = expf((S[nt][3] - m1) * 0.0625f); s1 += S[nt][3];
    }
    s0 += __shfl_xor_sync(0xffffffffu, s0, 1);
    s0 += __shfl_xor_sync(0xffffffffu, s0, 2);
    s1 += __shfl_xor_sync(0xffffffffu, s1, 1);
    s1 += __shfl_xor_sync(0xffffffffu, s1, 2);
    float i0 = 1.0f / s0, i1 = 1.0f / s1;
#pragma unroll
    for (int nt = 0; nt < 8; nt++) {
        S[nt][0] *= i0; S[nt][1] *= i0; S[nt][2] *= i1; S[nt][3] *= i1;
    }

    // write attention output
    const size_t ra = t0 + r0 + tq;
#pragma unroll
    for (int nt = 0; nt < 8; nt++) {
        float2 o0, o1;
        o0.x = S[nt][0]; o0.y = S[nt][1];
        o1.x = S[nt][2]; o1.y = S[nt][3];
        *(float2*)(att_out + ra * MS + nt * 8 + tr * 2)       = o0;
        *(float2*)(att_out + (ra + 8) * MS + nt * 8 + tr * 2) = o1;
    }

    // ---- repack P into A-fragments (register-only) ----
    uint32_t Ph[4][4], Pl[4][4];
#pragma unroll
    for (int kt = 0; kt < 4; kt++) {
        split2(S[2 * kt][0],     S[2 * kt][1],     Ph[kt][0], Pl[kt][0]);
        split2(S[2 * kt][2],     S[2 * kt][3],     Ph[kt][1], Pl[kt][1]);
        split2(S[2 * kt + 1][0], S[2 * kt + 1][1], Ph[kt][2], Pl[kt][2]);
        split2(S[2 * kt + 1][2], S[2 * kt + 1][3], Ph[kt][3], Pl[kt][3]);
    }

    // ---- weighted read: memo = P @ mem, 64 output cols at a time ----
    const int lr8 = lane & 7, kh = (lane >> 3) & 1, nh = lane >> 4;
#pragma unroll
    for (int nc = 0; nc < 4; nc++) {
        float acc2[8][4];
#pragma unroll
        for (int i = 0; i < 8; i++)
#pragma unroll
            for (int j = 0; j < 4; j++) acc2[i][j] = 0.0f;
#pragma unroll
        for (int kt = 0; kt < 4; kt++) {
#pragma unroll
            for (int g2 = 0; g2 < 4; g2++) {
                uint32_t boff = (uint32_t)(kt * 16 + kh * 8 + lr8) * EROW +
                                (nc * 64 + g2 * 16 + nh * 8) * 2;
                uint32_t bh[4], bl[4];
                ldsm_x4_t(bh, sMhi + boff);
                ldsm_x4_t(bl, sMlo + boff);
                mma16816(acc2[2 * g2],     Ph[kt], bh[0], bh[1]);
                mma16816(acc2[2 * g2 + 1], Ph[kt], bh[2], bh[3]);
                mma16816(acc2[2 * g2],     Ph[kt], bl[0], bl[1]);
                mma16816(acc2[2 * g2 + 1], Ph[kt], bl[2], bl[3]);
                mma16816(acc2[2 * g2],     Pl[kt], bh[0], bh[1]);
                mma16816(acc2[2 * g2 + 1], Pl[kt], bh[2], bh[3]);
            }
        }
        // write memo fp32 + bf16 hi/lo split for decode
#pragma unroll
        for (int nt2 = 0; nt2 < 8; nt2++) {
            int gc = nc * 64 + nt2 * 8 + tr * 2;
            float2 o0, o1;
            o0.x = acc2[nt2][0]; o0.y = acc2[nt2][1];
            o1.x = acc2[nt2][2]; o1.y = acc2[nt2][3];
            *(float2*)(mem_out + ra * DK + gc)       = o0;
            *(float2*)(mem_out + (ra + 8) * DK + gc) = o1;
            uint32_t h, l;
            split2(o0.x, o0.y, h, l);
            *(uint32_t*)(g_memo_hi + ra * DK + gc) = h;
            *(uint32_t*)(g_memo_lo + ra * DK + gc) = l;
            split2(o1.x, o1.y, h, l);
            *(uint32_t*)(g_memo_hi + (ra + 8) * DK + gc) = h;
            *(uint32_t*)(g_memo_lo + (ra + 8) * DK + gc) = l;
        }
    }
}

// ---------------------------------------------------------------------------
extern "C" void kernel_launch(void* const* d_in, const int* in_sizes, int n_in,
                              void* d_out, int out_size)
{
    const float* seq   = (const float*)d_in[0];
    const float* enc_w = (const float*)d_in[1];
    const float* enc_b = (const float*)d_in[2];
    const float* mem   = (const float*)d_in[3];
    const float* dec_w = (const float*)d_in[4];
    const float* dec_b = (const float*)d_in[5];

    float* recon = (float*)d_out;
    float* att   = recon + (size_t)NTOK * DIN;
    float* memo  = att   + (size_t)NTOK * MS;

    __nv_bfloat16 *encw_hi, *encw_lo, *decw_hi, *decw_lo;
    __nv_bfloat16 *enc_hi, *enc_lo, *memo_hi, *memo_lo;
    cudaGetSymbolAddress((void**)&encw_hi, g_encw_hi);
    cudaGetSymbolAddress((void**)&encw_lo, g_encw_lo);
    cudaGetSymbolAddress((void**)&decw_hi, g_decw_hi);
    cudaGetSymbolAddress((void**)&decw_lo, g_decw_lo);
    cudaGetSymbolAddress((void**)&enc_hi,  g_enc_hi);
    cudaGetSymbolAddress((void**)&enc_lo,  g_enc_lo);
    cudaGetSymbolAddress((void**)&memo_hi, g_memo_hi);
    cudaGetSymbolAddress((void**)&memo_lo, g_memo_lo);

    cudaFuncSetAttribute(hmma_gemm2<DIN, 0>,
                         cudaFuncAttributeMaxDynamicSharedMemorySize, GEMM_SMEM);
    cudaFuncSetAttribute(hmma_gemm2<DK, 1>,
                         cudaFuncAttributeMaxDynamicSharedMemorySize, GEMM_SMEM);
    cudaFuncSetAttribute(attn_mma,
                         cudaFuncAttributeMaxDynamicSharedMemorySize, AT_SMEM);

    // 0) split static tensors
    prep_split<<<264, 256>>>(enc_w, dec_w, mem);

    // 1) encode: tanh(seq @ enc_w^T + b) -> bf16 hi/lo
    dim3 g1(DK / 128, NTOK / 128);
    hmma_gemm2<DIN, 0><<<g1, 256, GEMM_SMEM>>>(
        seq, nullptr, nullptr, encw_hi, encw_lo, enc_b,
        nullptr, enc_hi, enc_lo, DK);

    // 2) attention + weighted read (HMMA)
    attn_mma<<<NTOK / 128, 256, AT_SMEM>>>(att, memo);

    // 3) decode: memo @ dec_w^T + b -> recon
    dim3 g3(DIN / 128, NTOK / 128);
    hmma_gemm2<DK, 1><<<g3, 256, GEMM_SMEM>>>(
        nullptr, memo_hi, memo_lo, decw_hi, decw_lo, dec_b,
        recon, nullptr, nullptr, DIN);
}

// round 6
// speedup vs baseline: 3.1804x; 1.4932x over previous
#include <cuda_runtime.h>
#include <cuda_bf16.h>
#include <cstdint>
#include <math.h>

#define NTOK  65536
#define DIN   512
#define DK    256
#define MS    64

// ---------------- static scratch ----------------
__device__ __nv_bfloat16 g_encw_hi[DK * DIN], g_encw_lo[DK * DIN];
__device__ __nv_bfloat16 g_mem_hi[MS * DK],  g_mem_lo[MS * DK];
__device__ __nv_bfloat16 g_enc_hi[(size_t)NTOK * DK], g_enc_lo[(size_t)NTOK * DK];
__device__ float         g_dt32[MS * DIN];                  // Dt[s][n] fp32
__device__ __nv_bfloat16 g_dt_hi[MS * DIN], g_dt_lo[MS * DIN];

// ======================= helpers =======================
__device__ __forceinline__ uint32_t smem_u32(const void* p) {
    uint32_t a;
    asm("{ .reg .u64 t; cvta.to.shared.u64 t, %1; cvt.u32.u64 %0, t; }"
        : "=r"(a) : "l"(p));
    return a;
}
__device__ __forceinline__ uint32_t pack_bf2(float a, float b) {
    __nv_bfloat162 t = __floats2bfloat162_rn(a, b);
    return *reinterpret_cast<uint32_t*>(&t);
}
__device__ __forceinline__ void split2(float a, float b, uint32_t& hi, uint32_t& lo) {
    __nv_bfloat16 ha = __float2bfloat16_rn(a), hb = __float2bfloat16_rn(b);
    __nv_bfloat162 hp; hp.x = ha; hp.y = hb;
    hi = *reinterpret_cast<uint32_t*>(&hp);
    lo = pack_bf2(a - __bfloat162float(ha), b - __bfloat162float(hb));
}
__device__ __forceinline__ void split4(float4 v, unsigned long long& hi,
                                       unsigned long long& lo) {
    uint32_t h0, l0, h1, l1;
    split2(v.x, v.y, h0, l0);
    split2(v.z, v.w, h1, l1);
    hi = (unsigned long long)h0 | ((unsigned long long)h1 << 32);
    lo = (unsigned long long)l0 | ((unsigned long long)l1 << 32);
}
__device__ __forceinline__ void sts64(uint32_t addr, unsigned long long v) {
    asm volatile("st.shared.b64 [%0], %1;" :: "r"(addr), "l"(v) : "memory");
}
__device__ __forceinline__ void cp16(uint32_t saddr, const void* g) {
    asm volatile("cp.async.cg.shared.global [%0], [%1], 16;"
                 :: "r"(saddr), "l"(g) : "memory");
}
#define CP_COMMIT() asm volatile("cp.async.commit_group;" ::: "memory")
#define CP_WAIT(n)  asm volatile("cp.async.wait_group %0;" :: "n"(n) : "memory")

__device__ __forceinline__ void ldsm_x4(uint32_t* r, uint32_t addr) {
    asm volatile("ldmatrix.sync.aligned.m8n8.x4.shared.b16 {%0,%1,%2,%3}, [%4];"
                 : "=r"(r[0]), "=r"(r[1]), "=r"(r[2]), "=r"(r[3]) : "r"(addr));
}
__device__ __forceinline__ void ldsm_x4_t(uint32_t* r, uint32_t addr) {
    asm volatile("ldmatrix.sync.aligned.m8n8.x4.trans.shared.b16 {%0,%1,%2,%3}, [%4];"
                 : "=r"(r[0]), "=r"(r[1]), "=r"(r[2]), "=r"(r[3]) : "r"(addr));
}
__device__ __forceinline__ void mma16816(float* d, const uint32_t* a,
                                         uint32_t b0, uint32_t b1) {
    asm volatile(
        "mma.sync.aligned.m16n8k16.row.col.f32.bf16.bf16.f32 "
        "{%0,%1,%2,%3}, {%4,%5,%6,%7}, {%8,%9}, {%0,%1,%2,%3};"
        : "+f"(d[0]), "+f"(d[1]), "+f"(d[2]), "+f"(d[3])
        : "r"(a[0]), "r"(a[1]), "r"(a[2]), "r"(a[3]), "r"(b0), "r"(b1));
}

// ---------------- prep 1: split enc_w and mem ----------------
__global__ void prep_split(const float* __restrict__ ew, const float* __restrict__ mm)
{
    int i = blockIdx.x * blockDim.x + threadIdx.x;
    int st = gridDim.x * blockDim.x;
    for (int j = i; j < DK * DIN; j += st) {
        float v = ew[j];
        __nv_bfloat16 h = __float2bfloat16_rn(v);
        g_encw_hi[j] = h;
        g_encw_lo[j] = __float2bfloat16_rn(v - __bfloat162float(h));
    }
    for (int j = i; j < MS * DK; j += st) {
        float v = mm[j];
        __nv_bfloat16 h = __float2bfloat16_rn(v);
        g_mem_hi[j] = h;
        g_mem_lo[j] = __float2bfloat16_rn(v - __bfloat162float(h));
    }
}

// ---------------- prep 2: Dt[s][n] = sum_k dec_w[n,k]*mem[s,k] ----------------
__global__ void prep_dt(const float* __restrict__ dw, const float* __restrict__ mm)
{
    int s = threadIdx.x & 63;
    int n = blockIdx.x * 4 + (threadIdx.x >> 6);
    const float4* wr = (const float4*)(dw + (size_t)n * DK);
    const float4* mr = (const float4*)(mm + (size_t)s * DK);
    float acc = 0.0f;
#pragma unroll 8
    for (int k = 0; k < DK / 4; k++) {
        float4 a = __ldg(wr + k), b = __ldg(mr + k);
        acc += a.x * b.x + a.y * b.y + a.z * b.z + a.w * b.w;
    }
    int idx = s * DIN + n;
    g_dt32[idx] = acc;
    __nv_bfloat16 h = __float2bfloat16_rn(acc);
    g_dt_hi[idx] = h;
    g_dt_lo[idx] = __float2bfloat16_rn(acc - __bfloat162float(h));
}

// ===========================================================================
// Encode GEMM: enc = tanh(seq @ enc_w^T + b) -> bf16 hi/lo.
// BM=128, BN=128, BK=32. A fp32 split in-kernel; W via cp.async (pre-split).
// Single __syncthreads per chunk.
// ===========================================================================
#define RSB   80
#define PART  (128 * RSB)
#define BUFSZ (4 * PART)
#define GEMM_SMEM (2 * BUFSZ)

__global__ void __launch_bounds__(256, 1)
enc_gemm(const float* __restrict__ A32, const float* __restrict__ bias)
{
    extern __shared__ char smc[];
    const uint32_t sb = smem_u32(smc);
    const int tid = threadIdx.x, wid = tid >> 5, lane = tid & 31;
    const int wm = wid & 3, wn = wid >> 2;
    const int NCH = DIN / 32;           // 16

    const size_t arow0 = (size_t)blockIdx.y * 128;
    const int n0 = blockIdx.x * 128;

    const int lrow = tid >> 3, lc4 = tid & 7;       // A fp32 map
    const int wrow = tid >> 1, wc16 = tid & 1;      // W cp.async map: 128r x 4x16B

    float acc[2][8][4];
#pragma unroll
    for (int i = 0; i < 2; i++)
#pragma unroll
        for (int j = 0; j < 8; j++)
#pragma unroll
            for (int k = 0; k < 4; k++) acc[i][j][k] = 0.0f;

    float4 av[4];

    auto issue_w = [&](int c, int buf) {
        const int k0 = c * 32;
        const uint32_t base = sb + buf * BUFSZ;
        uint32_t off = wrow * RSB + wc16 * 32;
        const __nv_bfloat16* gh = g_encw_hi + (size_t)(n0 + wrow) * DIN + k0 + wc16 * 16;
        const __nv_bfloat16* gl = g_encw_lo + (size_t)(n0 + wrow) * DIN + k0 + wc16 * 16;
        cp16(base + 2 * PART + off,      gh);
        cp16(base + 2 * PART + off + 16, gh + 8);
        cp16(base + 3 * PART + off,      gl);
        cp16(base + 3 * PART + off + 16, gl + 8);
    };
    auto load_a = [&](int c) {
        const int k0 = c * 32;
#pragma unroll
        for (int it = 0; it < 4; it++) {
            int row = lrow + it * 32;
            av[it] = __ldg((const float4*)(A32 + (arow0 + row) * DIN + k0 + lc4 * 4));
        }
    };
    auto store_a = [&](int buf) {
        const uint32_t base = sb + buf * BUFSZ;
#pragma unroll
        for (int it = 0; it < 4; it++) {
            int row = lrow + it * 32;
            uint32_t off = row * RSB + lc4 * 8;
            unsigned long long hi, lo;
            split4(av[it], hi, lo);
            sts64(base + off, hi);
            sts64(base + PART + off, lo);
        }
    };
    auto compute = [&](int buf) {
        const uint32_t base = sb + buf * BUFSZ;
        const uint32_t lr = lane & 15, lh = (lane >> 4) * 16;
#pragma unroll
        for (int ks = 0; ks < 2; ks++) {
            uint32_t ahf[2][4], alf[2][4], whf[4][4], wlf[4][4];
#pragma unroll
            for (int mt = 0; mt < 2; mt++) {
                uint32_t ao = (wm * 32 + mt * 16 + lr) * RSB + ks * 32 + lh;
                ldsm_x4(ahf[mt], base + ao);
                ldsm_x4(alf[mt], base + PART + ao);
            }
#pragma unroll
            for (int g = 0; g < 4; g++) {
                uint32_t wo = (wn * 64 + g * 16 + lr) * RSB + ks * 32 + lh;
                ldsm_x4(whf[g], base + 2 * PART + wo);
                ldsm_x4(wlf[g], base + 3 * PART + wo);
            }
#pragma unroll
            for (int mt = 0; mt < 2; mt++)
#pragma unroll
                for (int g = 0; g < 4; g++) {
                    mma16816(acc[mt][2 * g],     ahf[mt], whf[g][0], whf[g][2]);
                    mma16816(acc[mt][2 * g + 1], ahf[mt], whf[g][1], whf[g][3]);
                    mma16816(acc[mt][2 * g],     ahf[mt], wlf[g][0], wlf[g][2]);
                    mma16816(acc[mt][2 * g + 1], ahf[mt], wlf[g][1], wlf[g][3]);
                    mma16816(acc[mt][2 * g],     alf[mt], whf[g][0], whf[g][2]);
                    mma16816(acc[mt][2 * g + 1], alf[mt], whf[g][1], whf[g][3]);
                }
        }
    };

    // prologue
    issue_w(0, 0); CP_COMMIT();
    load_a(0); store_a(0);

    for (int c = 0; c < NCH; c++) {
        if (c + 1 < NCH) {
            issue_w(c + 1, (c + 1) & 1); CP_COMMIT();
            load_a(c + 1);
            CP_WAIT(1);                       // W(c) landed
        } else {
            CP_WAIT(0);
        }
        __syncthreads();                      // A(c) stores + W(c) visible
        compute(c & 1);
        if (c + 1 < NCH) store_a((c + 1) & 1);
    }

    // epilogue: tanh -> bf16 hi/lo
    const int tq = lane >> 2, tr = lane & 3;
#pragma unroll
    for (int mt = 0; mt < 2; mt++) {
        size_t r0 = arow0 + wm * 32 + mt * 16 + tq;
#pragma unroll
        for (int nt = 0; nt < 8; nt++) {
            int gn = n0 + wn * 64 + nt * 8 + tr * 2;
            float bx = bias[gn], by = bias[gn + 1];
            float v0 = tanhf(acc[mt][nt][0] + bx), v1 = tanhf(acc[mt][nt][1] + by);
            float v2 = tanhf(acc[mt][nt][2] + bx), v3 = tanhf(acc[mt][nt][3] + by);
            uint32_t h, l;
            split2(v0, v1, h, l);
            *(uint32_t*)(g_enc_hi + r0 * DK + gn) = h;
            *(uint32_t*)(g_enc_lo + r0 * DK + gn) = l;
            split2(v2, v3, h, l);
            *(uint32_t*)(g_enc_hi + (r0 + 8) * DK + gn) = h;
            *(uint32_t*)(g_enc_lo + (r0 + 8) * DK + gn) = l;
        }
    }
}

// ===========================================================================
// Fused attention + decode: 128 tokens/block, 8 warps.
//   S = E @ mem^T ; softmax in regs ; memo = P @ mem ;
//   recon = P @ Dt + dec_b  (Dt loaded into E's smem region after logits).
// ===========================================================================
#define EROW  528                    // 256 bf16 + pad, bytes
#define DTROW 1040                   // 512 bf16 + pad, bytes
#define AT_SMEM ((128 + 128 + 64 + 64) * EROW)   // 202752 B

__global__ void __launch_bounds__(256, 1)
attn_fused(float* __restrict__ att_out, float* __restrict__ mem_out,
           float* __restrict__ recon, const float* __restrict__ dec_b)
{
    extern __shared__ char smc[];
    const uint32_t sb = smem_u32(smc);
    const uint32_t sEhi = sb, sElo = sb + 128 * EROW;
    const uint32_t sMhi = sb + 256 * EROW, sMlo = sMhi + 64 * EROW;
    const uint32_t sDhi = sb, sDlo = sb + 64 * DTROW;   // overlays E after logits

    const int tid = threadIdx.x, wid = tid >> 5, lane = tid & 31;
    const size_t t0 = (size_t)blockIdx.x * 128;

    // load E tile + mem bank via cp.async
#pragma unroll
    for (int it = 0; it < 16; it++) {
        int idx = tid + it * 256;
        int row = idx >> 5, c = idx & 31;
        cp16(sEhi + row * EROW + c * 16, g_enc_hi + (t0 + row) * DK + c * 8);
        cp16(sElo + row * EROW + c * 16, g_enc_lo + (t0 + row) * DK + c * 8);
    }
#pragma unroll
    for (int it = 0; it < 8; it++) {
        int idx = tid + it * 256;
        int row = idx >> 5, c = idx & 31;
        cp16(sMhi + row * EROW + c * 16, g_mem_hi + row * DK + c * 8);
        cp16(sMlo + row * EROW + c * 16, g_mem_lo + row * DK + c * 8);
    }
    CP_COMMIT();
    CP_WAIT(0);
    __syncthreads();

    const int lr = lane & 15, half = lane >> 4;
    const int tq = lane >> 2, tr = lane & 3;
    const int r0 = wid * 16;

    // ---- logits S[128x64] ----
    float S[8][4];
#pragma unroll
    for (int i = 0; i < 8; i++)
#pragma unroll
        for (int j = 0; j < 4; j++) S[i][j] = 0.0f;

#pragma unroll
    for (int ks = 0; ks < 16; ks++) {
        uint32_t aoff = (r0 + lr) * EROW + ks * 32 + half * 16;
        uint32_t ahf[4], alf[4];
        ldsm_x4(ahf, sEhi + aoff);
        ldsm_x4(alf, sElo + aoff);
#pragma unroll
        for (int g = 0; g < 4; g++) {
            uint32_t woff = (g * 16 + lr) * EROW + ks * 32 + half * 16;
            uint32_t bh[4], bl[4];
            ldsm_x4(bh, sMhi + woff);
            ldsm_x4(bl, sMlo + woff);
            mma16816(S[2 * g],     ahf, bh[0], bh[2]);
            mma16816(S[2 * g + 1], ahf, bh[1], bh[3]);
            mma16816(S[2 * g],     ahf, bl[0], bl[2]);
            mma16816(S[2 * g + 1], ahf, bl[1], bl[3]);
            mma16816(S[2 * g],     alf, bh[0], bh[2]);
            mma16816(S[2 * g + 1], alf, bh[1], bh[3]);
        }
    }

    // ---- softmax (register-only) ----
    float m0 = -1e30f, m1 = -1e30f;
#pragma unroll
    for (int nt = 0; nt < 8; nt++) {
        m0 = fmaxf(m0, fmaxf(S[nt][0], S[nt][1]));
        m1 = fmaxf(m1, fmaxf(S[nt][2], S[nt][3]));
    }
    m0 = fmaxf(m0, __shfl_xor_sync(0xffffffffu, m0, 1));
    m0 = fmaxf(m0, __shfl_xor_sync(0xffffffffu, m0, 2));
    m1 = fmaxf(m1, __shfl_xor_sync(0xffffffffu, m1, 1));
    m1 = fmaxf(m1, __shfl_xor_sync(0xffffffffu, m1, 2));
    float s0 = 0.0f, s1 = 0.0f;
#pragma unroll
    for (int nt = 0; nt < 8; nt++) {
        S[nt][0] = expf((S[nt][0] - m0) * 0.0625f); s0 += S[nt][0];
        S[nt][1] = expf((S[nt][1] - m0) * 0.0625f); s0 += S[nt][1];
        S[nt][2] = expf((S[nt][2] - m1) * 0.0625f); s1 += S[nt][2];
        S[nt][3] = expf((S[nt][3] - m1) * 0.0625f); s1 += S[nt][3];
    }
    s0 += __shfl_xor_sync(0xffffffffu, s0, 1);
    s0 += __shfl_xor_sync(0xffffffffu, s0, 2);
    s1 += __shfl_xor_sync(0xffffffffu, s1, 1);
    s1 += __shfl_xor_sync(0xffffffffu, s1, 2);
    float i0 = 1.0f / s0, i1 = 1.0f / s1;
#pragma unroll
    for (int nt = 0; nt < 8; nt++) {
        S[nt][0] *= i0; S[nt][1] *= i0; S[nt][2] *= i1; S[nt][3] *= i1;
    }

    // ---- repack P into A-fragments ----
    uint32_t Ph[4][4], Pl[4][4];
#pragma unroll
    for (int kt = 0; kt < 4; kt++) {
        split2(S[2 * kt][0],     S[2 * kt][1],     Ph[kt][0], Pl[kt][0]);
        split2(S[2 * kt][2],     S[2 * kt][3],     Ph[kt][1], Pl[kt][1]);
        split2(S[2 * kt + 1][0], S[2 * kt + 1][1], Ph[kt][2], Pl[kt][2]);
        split2(S[2 * kt + 1][2], S[2 * kt + 1][3], Ph[kt][3], Pl[kt][3]);
    }

    __syncthreads();      // all warps done reading E region

    // issue Dt load into E region (overlapped with att write + memo phase)
#pragma unroll
    for (int it = 0; it < 16; it++) {
        int idx = tid + it * 256;
        int row = idx >> 6, c = idx & 63;
        cp16(sDhi + row * DTROW + c * 16, g_dt_hi + row * DIN + c * 8);
        cp16(sDlo + row * DTROW + c * 16, g_dt_lo + row * DIN + c * 8);
    }
    CP_COMMIT();

    // write attention output
    const size_t ra = t0 + r0 + tq;
#pragma unroll
    for (int nt = 0; nt < 8; nt++) {
        float2 o0, o1;
        o0.x = S[nt][0]; o0.y = S[nt][1];
        o1.x = S[nt][2]; o1.y = S[nt][3];
        *(float2*)(att_out + ra * MS + nt * 8 + tr * 2)       = o0;
        *(float2*)(att_out + (ra + 8) * MS + nt * 8 + tr * 2) = o1;
    }

    // ---- memo = P @ mem (mem smem untouched) ----
    const int lr8 = lane & 7, kh = (lane >> 3) & 1, nh = lane >> 4;
#pragma unroll
    for (int nc = 0; nc < 4; nc++) {
        float acc2[8][4];
#pragma unroll
        for (int i = 0; i < 8; i++)
#pragma unroll
            for (int j = 0; j < 4; j++) acc2[i][j] = 0.0f;
#pragma unroll
        for (int kt = 0; kt < 4; kt++) {
#pragma unroll
            for (int g2 = 0; g2 < 4; g2++) {
                uint32_t boff = (uint32_t)(kt * 16 + kh * 8 + lr8) * EROW +
                                (nc * 64 + g2 * 16 + nh * 8) * 2;
                uint32_t bh[4], bl[4];
                ldsm_x4_t(bh, sMhi + boff);
                ldsm_x4_t(bl, sMlo + boff);
                mma16816(acc2[2 * g2],     Ph[kt], bh[0], bh[1]);
                mma16816(acc2[2 * g2 + 1], Ph[kt], bh[2], bh[3]);
                mma16816(acc2[2 * g2],     Ph[kt], bl[0], bl[1]);
                mma16816(acc2[2 * g2 + 1], Ph[kt], bl[2], bl[3]);
                mma16816(acc2[2 * g2],     Pl[kt], bh[0], bh[1]);
                mma16816(acc2[2 * g2 + 1], Pl[kt], bh[2], bh[3]);
            }
        }
#pragma unroll
        for (int nt2 = 0; nt2 < 8; nt2++) {
            int gc = nc * 64 + nt2 * 8 + tr * 2;
            float2 o0, o1;
            o0.x = acc2[nt2][0]; o0.y = acc2[nt2][1];
            o1.x = acc2[nt2][2]; o1.y = acc2[nt2][3];
            *(float2*)(mem_out + ra * DK + gc)       = o0;
            *(float2*)(mem_out + (ra + 8) * DK + gc) = o1;
        }
    }

    CP_WAIT(0);
    __syncthreads();      // Dt visible to all threads

    // ---- recon = P @ Dt + dec_b ----
#pragma unroll
    for (int nc = 0; nc < 8; nc++) {
        float acc2[8][4];
#pragma unroll
        for (int i = 0; i < 8; i++)
#pragma unroll
            for (int j = 0; j < 4; j++) acc2[i][j] = 0.0f;
#pragma unroll
        for (int kt = 0; kt < 4; kt++) {
#pragma unroll
            for (int g2 = 0; g2 < 4; g2++) {
                uint32_t boff = (uint32_t)(kt * 16 + kh * 8 + lr8) * DTROW +
                                (nc * 64 + g2 * 16 + nh * 8) * 2;
                uint32_t bh[4], bl[4];
                ldsm_x4_t(bh, sDhi + boff);
                ldsm_x4_t(bl, sDlo + boff);
                mma16816(acc2[2 * g2],     Ph[kt], bh[0], bh[1]);
                mma16816(acc2[2 * g2 + 1], Ph[kt], bh[2], bh[3]);
                mma16816(acc2[2 * g2],     Ph[kt], bl[0], bl[1]);
                mma16816(acc2[2 * g2 + 1], Ph[kt], bl[2], bl[3]);
                mma16816(acc2[2 * g2],     Pl[kt], bh[0], bh[1]);
                mma16816(acc2[2 * g2 + 1], Pl[kt], bh[2], bh[3]);
            }
        }
#pragma unroll
        for (int nt2 = 0; nt2 < 8; nt2++) {
            int gc = nc * 64 + nt2 * 8 + tr * 2;
            float2 b2 = *(const float2*)(dec_b + gc);
            float2 o0, o1;
            o0.x = acc2[nt2][0] + b2.x; o0.y = acc2[nt2][1] + b2.y;
            o1.x = acc2[nt2][2] + b2.x; o1.y = acc2[nt2][3] + b2.y;
            *(float2*)(recon + ra * DIN + gc)       = o0;
            *(float2*)(recon + (ra + 8) * DIN + gc) = o1;
        }
    }
}

// ---------------------------------------------------------------------------
extern "C" void kernel_launch(void* const* d_in, const int* in_sizes, int n_in,
                              void* d_out, int out_size)
{
    const float* seq   = (const float*)d_in[0];
    const float* enc_w = (const float*)d_in[1];
    const float* enc_b = (const float*)d_in[2];
    const float* mem   = (const float*)d_in[3];
    const float* dec_w = (const float*)d_in[4];
    const float* dec_b = (const float*)d_in[5];

    float* recon = (float*)d_out;
    float* att   = recon + (size_t)NTOK * DIN;
    float* memo  = att   + (size_t)NTOK * MS;

    cudaFuncSetAttribute(enc_gemm,
                         cudaFuncAttributeMaxDynamicSharedMemorySize, GEMM_SMEM);
    cudaFuncSetAttribute(attn_fused,
                         cudaFuncAttributeMaxDynamicSharedMemorySize, AT_SMEM);

    // 0) prep: splits + Dt = dec_w @ mem^T
    prep_split<<<160, 256>>>(enc_w, mem);
    prep_dt<<<DIN / 4, 256>>>(dec_w, mem);

    // 1) encode
    dim3 g1(DK / 128, NTOK / 128);
    enc_gemm<<<g1, 256, GEMM_SMEM>>>(seq, enc_b);

    // 2) fused attention + weighted read + decode
    attn_fused<<<NTOK / 128, 256, AT_SMEM>>>(att, memo, recon, dec_b);
}

// round 7
// speedup vs baseline: 3.1884x; 1.0025x over previous
#include <cuda_runtime.h>
#include <cuda_bf16.h>
#include <cstdint>
#include <math.h>

#define NTOK  65536
#define DIN   512
#define DK    256
#define MS    64

// ---------------- static scratch ----------------
__device__ __nv_bfloat16 g_encw_hi[DK * DIN], g_encw_lo[DK * DIN];
__device__ __nv_bfloat16 g_mem_hi[MS * DK],  g_mem_lo[MS * DK];
__device__ __nv_bfloat16 g_enc_hi[(size_t)NTOK * DK], g_enc_lo[(size_t)NTOK * DK];
__device__ __nv_bfloat16 g_dt_hi[MS * DIN], g_dt_lo[MS * DIN];

// ======================= helpers =======================
__device__ __forceinline__ uint32_t smem_u32(const void* p) {
    uint32_t a;
    asm("{ .reg .u64 t; cvta.to.shared.u64 t, %1; cvt.u32.u64 %0, t; }"
        : "=r"(a) : "l"(p));
    return a;
}
__device__ __forceinline__ uint32_t pack_bf2(float a, float b) {
    __nv_bfloat162 t = __floats2bfloat162_rn(a, b);
    return *reinterpret_cast<uint32_t*>(&t);
}
__device__ __forceinline__ void split2(float a, float b, uint32_t& hi, uint32_t& lo) {
    __nv_bfloat16 ha = __float2bfloat16_rn(a), hb = __float2bfloat16_rn(b);
    __nv_bfloat162 hp; hp.x = ha; hp.y = hb;
    hi = *reinterpret_cast<uint32_t*>(&hp);
    lo = pack_bf2(a - __bfloat162float(ha), b - __bfloat162float(hb));
}
__device__ __forceinline__ void split4(float4 v, unsigned long long& hi,
                                       unsigned long long& lo) {
    uint32_t h0, l0, h1, l1;
    split2(v.x, v.y, h0, l0);
    split2(v.z, v.w, h1, l1);
    hi = (unsigned long long)h0 | ((unsigned long long)h1 << 32);
    lo = (unsigned long long)l0 | ((unsigned long long)l1 << 32);
}
__device__ __forceinline__ void sts64(uint32_t addr, unsigned long long v) {
    asm volatile("st.shared.b64 [%0], %1;" :: "r"(addr), "l"(v) : "memory");
}
__device__ __forceinline__ void cp16(uint32_t saddr, const void* g) {
    asm volatile("cp.async.cg.shared.global [%0], [%1], 16;"
                 :: "r"(saddr), "l"(g) : "memory");
}
#define CP_COMMIT() asm volatile("cp.async.commit_group;" ::: "memory")
#define CP_WAIT(n)  asm volatile("cp.async.wait_group %0;" :: "n"(n) : "memory")

__device__ __forceinline__ void ldsm_x4(uint32_t* r, uint32_t addr) {
    asm volatile("ldmatrix.sync.aligned.m8n8.x4.shared.b16 {%0,%1,%2,%3}, [%4];"
                 : "=r"(r[0]), "=r"(r[1]), "=r"(r[2]), "=r"(r[3]) : "r"(addr));
}
__device__ __forceinline__ void ldsm_x4_t(uint32_t* r, uint32_t addr) {
    asm volatile("ldmatrix.sync.aligned.m8n8.x4.trans.shared.b16 {%0,%1,%2,%3}, [%4];"
                 : "=r"(r[0]), "=r"(r[1]), "=r"(r[2]), "=r"(r[3]) : "r"(addr));
}
__device__ __forceinline__ void mma16816(float* d, const uint32_t* a,
                                         uint32_t b0, uint32_t b1) {
    asm volatile(
        "mma.sync.aligned.m16n8k16.row.col.f32.bf16.bf16.f32 "
        "{%0,%1,%2,%3}, {%4,%5,%6,%7}, {%8,%9}, {%0,%1,%2,%3};"
        : "+f"(d[0]), "+f"(d[1]), "+f"(d[2]), "+f"(d[3])
        : "r"(a[0]), "r"(a[1]), "r"(a[2]), "r"(a[3]), "r"(b0), "r"(b1));
}

// ---------------- prep 1: split enc_w and mem ----------------
__global__ void prep_split(const float* __restrict__ ew, const float* __restrict__ mm)
{
    int i = blockIdx.x * blockDim.x + threadIdx.x;
    int st = gridDim.x * blockDim.x;
    for (int j = i; j < DK * DIN; j += st) {
        float v = ew[j];
        __nv_bfloat16 h = __float2bfloat16_rn(v);
        g_encw_hi[j] = h;
        g_encw_lo[j] = __float2bfloat16_rn(v - __bfloat162float(h));
    }
    for (int j = i; j < MS * DK; j += st) {
        float v = mm[j];
        __nv_bfloat16 h = __float2bfloat16_rn(v);
        g_mem_hi[j] = h;
        g_mem_lo[j] = __float2bfloat16_rn(v - __bfloat162float(h));
    }
}

// ---------------- prep 2: Dt[s][n] = sum_k dec_w[n,k]*mem[s,k] ----------------
__global__ void prep_dt(const float* __restrict__ dw, const float* __restrict__ mm)
{
    int s = threadIdx.x & 63;
    int n = blockIdx.x * 4 + (threadIdx.x >> 6);
    const float4* wr = (const float4*)(dw + (size_t)n * DK);
    const float4* mr = (const float4*)(mm + (size_t)s * DK);
    float acc = 0.0f;
#pragma unroll 8
    for (int k = 0; k < DK / 4; k++) {
        float4 a = __ldg(wr + k), b = __ldg(mr + k);
        acc += a.x * b.x + a.y * b.y + a.z * b.z + a.w * b.w;
    }
    int idx = s * DIN + n;
    __nv_bfloat16 h = __float2bfloat16_rn(acc);
    g_dt_hi[idx] = h;
    g_dt_lo[idx] = __float2bfloat16_rn(acc - __bfloat162float(h));
}

// ===========================================================================
// Encode GEMM: enc = tanh(seq @ enc_w^T + b) -> bf16 hi/lo.
// Pass-major MMA ordering for ILP.
// ===========================================================================
#define RSB   80
#define PART  (128 * RSB)
#define BUFSZ (4 * PART)
#define GEMM_SMEM (2 * BUFSZ)

__global__ void __launch_bounds__(256, 1)
enc_gemm(const float* __restrict__ A32, const float* __restrict__ bias)
{
    extern __shared__ char smc[];
    const uint32_t sb = smem_u32(smc);
    const int tid = threadIdx.x, wid = tid >> 5, lane = tid & 31;
    const int wm = wid & 3, wn = wid >> 2;
    const int NCH = DIN / 32;           // 16

    const size_t arow0 = (size_t)blockIdx.y * 128;
    const int n0 = blockIdx.x * 128;

    const int lrow = tid >> 3, lc4 = tid & 7;
    const int wrow = tid >> 1, wc16 = tid & 1;

    float acc[2][8][4];
#pragma unroll
    for (int i = 0; i < 2; i++)
#pragma unroll
        for (int j = 0; j < 8; j++)
#pragma unroll
            for (int k = 0; k < 4; k++) acc[i][j][k] = 0.0f;

    float4 av[4];

    auto issue_w = [&](int c, int buf) {
        const int k0 = c * 32;
        const uint32_t base = sb + buf * BUFSZ;
        uint32_t off = wrow * RSB + wc16 * 32;
        const __nv_bfloat16* gh = g_encw_hi + (size_t)(n0 + wrow) * DIN + k0 + wc16 * 16;
        const __nv_bfloat16* gl = g_encw_lo + (size_t)(n0 + wrow) * DIN + k0 + wc16 * 16;
        cp16(base + 2 * PART + off,      gh);
        cp16(base + 2 * PART + off + 16, gh + 8);
        cp16(base + 3 * PART + off,      gl);
        cp16(base + 3 * PART + off + 16, gl + 8);
    };
    auto load_a = [&](int c) {
        const int k0 = c * 32;
#pragma unroll
        for (int it = 0; it < 4; it++) {
            int row = lrow + it * 32;
            av[it] = __ldg((const float4*)(A32 + (arow0 + row) * DIN + k0 + lc4 * 4));
        }
    };
    auto store_a = [&](int buf) {
        const uint32_t base = sb + buf * BUFSZ;
#pragma unroll
        for (int it = 0; it < 4; it++) {
            int row = lrow + it * 32;
            uint32_t off = row * RSB + lc4 * 8;
            unsigned long long hi, lo;
            split4(av[it], hi, lo);
            sts64(base + off, hi);
            sts64(base + PART + off, lo);
        }
    };
    auto compute = [&](int buf) {
        const uint32_t base = sb + buf * BUFSZ;
        const uint32_t lr = lane & 15, lh = (lane >> 4) * 16;
#pragma unroll
        for (int ks = 0; ks < 2; ks++) {
            uint32_t ahf[2][4], alf[2][4], whf[4][4], wlf[4][4];
#pragma unroll
            for (int mt = 0; mt < 2; mt++) {
                uint32_t ao = (wm * 32 + mt * 16 + lr) * RSB + ks * 32 + lh;
                ldsm_x4(ahf[mt], base + ao);
                ldsm_x4(alf[mt], base + PART + ao);
            }
#pragma unroll
            for (int g = 0; g < 4; g++) {
                uint32_t wo = (wn * 64 + g * 16 + lr) * RSB + ks * 32 + lh;
                ldsm_x4(whf[g], base + 2 * PART + wo);
                ldsm_x4(wlf[g], base + 3 * PART + wo);
            }
            // pass 1: hi x hi  (16 independent MMAs)
#pragma unroll
            for (int mt = 0; mt < 2; mt++)
#pragma unroll
                for (int g = 0; g < 4; g++) {
                    mma16816(acc[mt][2 * g],     ahf[mt], whf[g][0], whf[g][2]);
                    mma16816(acc[mt][2 * g + 1], ahf[mt], whf[g][1], whf[g][3]);
                }
            // pass 2: hi x lo
#pragma unroll
            for (int mt = 0; mt < 2; mt++)
#pragma unroll
                for (int g = 0; g < 4; g++) {
                    mma16816(acc[mt][2 * g],     ahf[mt], wlf[g][0], wlf[g][2]);
                    mma16816(acc[mt][2 * g + 1], ahf[mt], wlf[g][1], wlf[g][3]);
                }
            // pass 3: lo x hi
#pragma unroll
            for (int mt = 0; mt < 2; mt++)
#pragma unroll
                for (int g = 0; g < 4; g++) {
                    mma16816(acc[mt][2 * g],     alf[mt], whf[g][0], whf[g][2]);
                    mma16816(acc[mt][2 * g + 1], alf[mt], whf[g][1], whf[g][3]);
                }
        }
    };

    issue_w(0, 0); CP_COMMIT();
    load_a(0); store_a(0);

    for (int c = 0; c < NCH; c++) {
        if (c + 1 < NCH) {
            issue_w(c + 1, (c + 1) & 1); CP_COMMIT();
            load_a(c + 1);
            CP_WAIT(1);
        } else {
            CP_WAIT(0);
        }
        __syncthreads();
        compute(c & 1);
        if (c + 1 < NCH) store_a((c + 1) & 1);
    }

    const int tq = lane >> 2, tr = lane & 3;
#pragma unroll
    for (int mt = 0; mt < 2; mt++) {
        size_t r0 = arow0 + wm * 32 + mt * 16 + tq;
#pragma unroll
        for (int nt = 0; nt < 8; nt++) {
            int gn = n0 + wn * 64 + nt * 8 + tr * 2;
            float bx = bias[gn], by = bias[gn + 1];
            float v0 = tanhf(acc[mt][nt][0] + bx), v1 = tanhf(acc[mt][nt][1] + by);
            float v2 = tanhf(acc[mt][nt][2] + bx), v3 = tanhf(acc[mt][nt][3] + by);
            uint32_t h, l;
            split2(v0, v1, h, l);
            *(uint32_t*)(g_enc_hi + r0 * DK + gn) = h;
            *(uint32_t*)(g_enc_lo + r0 * DK + gn) = l;
            split2(v2, v3, h, l);
            *(uint32_t*)(g_enc_hi + (r0 + 8) * DK + gn) = h;
            *(uint32_t*)(g_enc_lo + (r0 + 8) * DK + gn) = l;
        }
    }
}

// ===========================================================================
// Fused attention + decode, pass-major MMA ordering.
// ===========================================================================
#define EROW  528
#define DTROW 1040
#define AT_SMEM ((128 + 128 + 64 + 64) * EROW)   // 202752 B

__global__ void __launch_bounds__(256, 1)
attn_fused(float* __restrict__ att_out, float* __restrict__ mem_out,
           float* __restrict__ recon, const float* __restrict__ dec_b)
{
    extern __shared__ char smc[];
    const uint32_t sb = smem_u32(smc);
    const uint32_t sEhi = sb, sElo = sb + 128 * EROW;
    const uint32_t sMhi = sb + 256 * EROW, sMlo = sMhi + 64 * EROW;
    const uint32_t sDhi = sb, sDlo = sb + 64 * DTROW;

    const int tid = threadIdx.x, wid = tid >> 5, lane = tid & 31;
    const size_t t0 = (size_t)blockIdx.x * 128;

#pragma unroll
    for (int it = 0; it < 16; it++) {
        int idx = tid + it * 256;
        int row = idx >> 5, c = idx & 31;
        cp16(sEhi + row * EROW + c * 16, g_enc_hi + (t0 + row) * DK + c * 8);
        cp16(sElo + row * EROW + c * 16, g_enc_lo + (t0 + row) * DK + c * 8);
    }
#pragma unroll
    for (int it = 0; it < 8; it++) {
        int idx = tid + it * 256;
        int row = idx >> 5, c = idx & 31;
        cp16(sMhi + row * EROW + c * 16, g_mem_hi + row * DK + c * 8);
        cp16(sMlo + row * EROW + c * 16, g_mem_lo + row * DK + c * 8);
    }
    CP_COMMIT();
    CP_WAIT(0);
    __syncthreads();

    const int lr = lane & 15, half = lane >> 4;
    const int tq = lane >> 2, tr = lane & 3;
    const int r0 = wid * 16;

    // ---- logits S[128x64], pass-major ----
    float S[8][4];
#pragma unroll
    for (int i = 0; i < 8; i++)
#pragma unroll
        for (int j = 0; j < 4; j++) S[i][j] = 0.0f;

#pragma unroll
    for (int ks = 0; ks < 16; ks++) {
        uint32_t aoff = (r0 + lr) * EROW + ks * 32 + half * 16;
        uint32_t ahf[4], alf[4], bh[4][4], bl[4][4];
        ldsm_x4(ahf, sEhi + aoff);
        ldsm_x4(alf, sElo + aoff);
#pragma unroll
        for (int g = 0; g < 4; g++) {
            uint32_t woff = (g * 16 + lr) * EROW + ks * 32 + half * 16;
            ldsm_x4(bh[g], sMhi + woff);
            ldsm_x4(bl[g], sMlo + woff);
        }
#pragma unroll
        for (int g = 0; g < 4; g++) {
            mma16816(S[2 * g],     ahf, bh[g][0], bh[g][2]);
            mma16816(S[2 * g + 1], ahf, bh[g][1], bh[g][3]);
        }
#pragma unroll
        for (int g = 0; g < 4; g++) {
            mma16816(S[2 * g],     ahf, bl[g][0], bl[g][2]);
            mma16816(S[2 * g + 1], ahf, bl[g][1], bl[g][3]);
        }
#pragma unroll
        for (int g = 0; g < 4; g++) {
            mma16816(S[2 * g],     alf, bh[g][0], bh[g][2]);
            mma16816(S[2 * g + 1], alf, bh[g][1], bh[g][3]);
        }
    }

    // ---- softmax (register-only) ----
    float m0 = -1e30f, m1 = -1e30f;
#pragma unroll
    for (int nt = 0; nt < 8; nt++) {
        m0 = fmaxf(m0, fmaxf(S[nt][0], S[nt][1]));
        m1 = fmaxf(m1, fmaxf(S[nt][2], S[nt][3]));
    }
    m0 = fmaxf(m0, __shfl_xor_sync(0xffffffffu, m0, 1));
    m0 = fmaxf(m0, __shfl_xor_sync(0xffffffffu, m0, 2));
    m1 = fmaxf(m1, __shfl_xor_sync(0xffffffffu, m1, 1));
    m1 = fmaxf(m1, __shfl_xor_sync(0xffffffffu, m1, 2));
    float s0 = 0.0f, s1 = 0.0f;
#pragma unroll
    for (int nt = 0; nt < 8; nt++) {
        S[nt][0] = expf((S[nt][0] - m0) * 0.0625f); s0 += S[nt][0];
        S[nt][1] = expf((S[nt][1] - m0) * 0.0625f); s0 += S[nt][1];
        S[nt][2] = expf((S[nt][2] - m1) * 0.0625f); s1 += S[nt][2];
        S[nt][3] = expf((S[nt][3] - m1) * 0.0625f); s1 += S[nt][3];
    }
    s0 += __shfl_xor_sync(0xffffffffu, s0, 1);
    s0 += __shfl_xor_sync(0xffffffffu, s0, 2);
    s1 += __shfl_xor_sync(0xffffffffu, s1, 1);
    s1 += __shfl_xor_sync(0xffffffffu, s1, 2);
    float i0 = 1.0f / s0, i1 = 1.0f / s1;
#pragma unroll
    for (int nt = 0; nt < 8; nt++) {
        S[nt][0] *= i0; S[nt][1] *= i0; S[nt][2] *= i1; S[nt][3] *= i1;
    }

    // ---- repack P into A-fragments ----
    uint32_t Ph[4][4], Pl[4][4];
#pragma unroll
    for (int kt = 0; kt < 4; kt++) {
        split2(S[2 * kt][0],     S[2 * kt][1],     Ph[kt][0], Pl[kt][0]);
        split2(S[2 * kt][2],     S[2 * kt][3],     Ph[kt][1], Pl[kt][1]);
        split2(S[2 * kt + 1][0], S[2 * kt + 1][1], Ph[kt][2], Pl[kt][2]);
        split2(S[2 * kt + 1][2], S[2 * kt + 1][3], Ph[kt][3], Pl[kt][3]);
    }

    __syncthreads();

    // Dt load into E region (overlapped)
#pragma unroll
    for (int it = 0; it < 16; it++) {
        int idx = tid + it * 256;
        int row = idx >> 6, c = idx & 63;
        cp16(sDhi + row * DTROW + c * 16, g_dt_hi + row * DIN + c * 8);
        cp16(sDlo + row * DTROW + c * 16, g_dt_lo + row * DIN + c * 8);
    }
    CP_COMMIT();

    // attention output
    const size_t ra = t0 + r0 + tq;
#pragma unroll
    for (int nt = 0; nt < 8; nt++) {
        float2 o0, o1;
        o0.x = S[nt][0]; o0.y = S[nt][1];
        o1.x = S[nt][2]; o1.y = S[nt][3];
        *(float2*)(att_out + ra * MS + nt * 8 + tr * 2)       = o0;
        *(float2*)(att_out + (ra + 8) * MS + nt * 8 + tr * 2) = o1;
    }

    // ---- memo = P @ mem, pass-major per kt ----
    const int lr8 = lane & 7, kh = (lane >> 3) & 1, nh = lane >> 4;
#pragma unroll
    for (int nc = 0; nc < 4; nc++) {
        float acc2[8][4];
#pragma unroll
        for (int i = 0; i < 8; i++)
#pragma unroll
            for (int j = 0; j < 4; j++) acc2[i][j] = 0.0f;
#pragma unroll
        for (int kt = 0; kt < 4; kt++) {
            uint32_t bh[4][4], bl[4][4];
#pragma unroll
            for (int g2 = 0; g2 < 4; g2++) {
                uint32_t boff = (uint32_t)(kt * 16 + kh * 8 + lr8) * EROW +
                                (nc * 64 + g2 * 16 + nh * 8) * 2;
                ldsm_x4_t(bh[g2], sMhi + boff);
                ldsm_x4_t(bl[g2], sMlo + boff);
            }
#pragma unroll
            for (int g2 = 0; g2 < 4; g2++) {
                mma16816(acc2[2 * g2],     Ph[kt], bh[g2][0], bh[g2][1]);
                mma16816(acc2[2 * g2 + 1], Ph[kt], bh[g2][2], bh[g2][3]);
            }
#pragma unroll
            for (int g2 = 0; g2 < 4; g2++) {
                mma16816(acc2[2 * g2],     Ph[kt], bl[g2][0], bl[g2][1]);
                mma16816(acc2[2 * g2 + 1], Ph[kt], bl[g2][2], bl[g2][3]);
            }
#pragma unroll
            for (int g2 = 0; g2 < 4; g2++) {
                mma16816(acc2[2 * g2],     Pl[kt], bh[g2][0], bh[g2][1]);
                mma16816(acc2[2 * g2 + 1], Pl[kt], bh[g2][2], bh[g2][3]);
            }
        }
#pragma unroll
        for (int nt2 = 0; nt2 < 8; nt2++) {
            int gc = nc * 64 + nt2 * 8 + tr * 2;
            float2 o0, o1;
            o0.x = acc2[nt2][0]; o0.y = acc2[nt2][1];
            o1.x = acc2[nt2][2]; o1.y = acc2[nt2][3];
            *(float2*)(mem_out + ra * DK + gc)       = o0;
            *(float2*)(mem_out + (ra + 8) * DK + gc) = o1;
        }
    }

    CP_WAIT(0);
    __syncthreads();

    // ---- recon = P @ Dt + dec_b, pass-major per (nc,kt) ----
#pragma unroll
    for (int nc = 0; nc < 8; nc++) {
        float acc2[8][4];
#pragma unroll
        for (int i = 0; i < 8; i++)
#pragma unroll
            for (int j = 0; j < 4; j++) acc2[i][j] = 0.0f;
#pragma unroll
        for (int kt = 0; kt < 4; kt++) {
            uint32_t bh[4][4], bl[4][4];
#pragma unroll
            for (int g2 = 0; g2 < 4; g2++) {
                uint32_t boff = (uint32_t)(kt * 16 + kh * 8 + lr8) * DTROW +
                                (nc * 64 + g2 * 16 + nh * 8) * 2;
                ldsm_x4_t(bh[g2], sDhi + boff);
                ldsm_x4_t(bl[g2], sDlo + boff);
            }
#pragma unroll
            for (int g2 = 0; g2 < 4; g2++) {
                mma16816(acc2[2 * g2],     Ph[kt], bh[g2][0], bh[g2][1]);
                mma16816(acc2[2 * g2 + 1], Ph[kt], bh[g2][2], bh[g2][3]);
            }
#pragma unroll
            for (int g2 = 0; g2 < 4; g2++) {
                mma16816(acc2[2 * g2],     Ph[kt], bl[g2][0], bl[g2][1]);
                mma16816(acc2[2 * g2 + 1], Ph[kt], bl[g2][2], bl[g2][3]);
            }
#pragma unroll
            for (int g2 = 0; g2 < 4; g2++) {
                mma16816(acc2[2 * g2],     Pl[kt], bh[g2][0], bh[g2][1]);
                mma16816(acc2[2 * g2 + 1], Pl[kt], bh[g2][2], bh[g2][3]);
            }
        }
#pragma unroll
        for (int nt2 = 0; nt2 < 8; nt2++) {
            int gc = nc * 64 + nt2 * 8 + tr * 2;
            float2 b2 = *(const float2*)(dec_b + gc);
            float2 o0, o1;
            o0.x = acc2[nt2][0] + b2.x; o0.y = acc2[nt2][1] + b2.y;
            o1.x = acc2[nt2][2] + b2.x; o1.y = acc2[nt2][3] + b2.y;
            *(float2*)(recon + ra * DIN + gc)       = o0;
            *(float2*)(recon + (ra + 8) * DIN + gc) = o1;
        }
    }
}

// ---------------------------------------------------------------------------
extern "C" void kernel_launch(void* const* d_in, const int* in_sizes, int n_in,
                              void* d_out, int out_size)
{
    const float* seq   = (const float*)d_in[0];
    const float* enc_w = (const float*)d_in[1];
    const float* enc_b = (const float*)d_in[2];
    const float* mem   = (const float*)d_in[3];
    const float* dec_w = (const float*)d_in[4];
    const float* dec_b = (const float*)d_in[5];

    float* recon = (float*)d_out;
    float* att   = recon + (size_t)NTOK * DIN;
    float* memo  = att   + (size_t)NTOK * MS;

    cudaFuncSetAttribute(enc_gemm,
                         cudaFuncAttributeMaxDynamicSharedMemorySize, GEMM_SMEM);
    cudaFuncSetAttribute(attn_fused,
                         cudaFuncAttributeMaxDynamicSharedMemorySize, AT_SMEM);

    prep_split<<<160, 256>>>(enc_w, mem);
    prep_dt<<<DIN / 4, 256>>>(dec_w, mem);

    dim3 g1(DK / 128, NTOK / 128);
    enc_gemm<<<g1, 256, GEMM_SMEM>>>(seq, enc_b);

    attn_fused<<<NTOK / 128, 256, AT_SMEM>>>(att, memo, recon, dec_b);
}

// round 8
// speedup vs baseline: 3.5525x; 1.1142x over previous
#include <cuda_runtime.h>
#include <cuda_bf16.h>
#include <cstdint>
#include <math.h>

#define NTOK  65536
#define DIN   512
#define DK    256
#define MS    64

// ---------------- static scratch ----------------
__device__ __nv_bfloat16 g_encw_hi[DK * DIN], g_encw_lo[DK * DIN];
__device__ __nv_bfloat16 g_mem_hi[MS * DK],  g_mem_lo[MS * DK];
__device__ __nv_bfloat16 g_enc_hi[(size_t)NTOK * DK], g_enc_lo[(size_t)NTOK * DK];
__device__ __nv_bfloat16 g_dt_hi[MS * DIN], g_dt_lo[MS * DIN];

// ======================= helpers =======================
__device__ __forceinline__ uint32_t smem_u32(const void* p) {
    uint32_t a;
    asm("{ .reg .u64 t; cvta.to.shared.u64 t, %1; cvt.u32.u64 %0, t; }"
        : "=r"(a) : "l"(p));
    return a;
}
__device__ __forceinline__ uint32_t pack_bf2(float a, float b) {
    __nv_bfloat162 t = __floats2bfloat162_rn(a, b);
    return *reinterpret_cast<uint32_t*>(&t);
}
__device__ __forceinline__ void split2(float a, float b, uint32_t& hi, uint32_t& lo) {
    __nv_bfloat16 ha = __float2bfloat16_rn(a), hb = __float2bfloat16_rn(b);
    __nv_bfloat162 hp; hp.x = ha; hp.y = hb;
    hi = *reinterpret_cast<uint32_t*>(&hp);
    lo = pack_bf2(a - __bfloat162float(ha), b - __bfloat162float(hb));
}
__device__ __forceinline__ void split4(float4 v, unsigned long long& hi,
                                       unsigned long long& lo) {
    uint32_t h0, l0, h1, l1;
    split2(v.x, v.y, h0, l0);
    split2(v.z, v.w, h1, l1);
    hi = (unsigned long long)h0 | ((unsigned long long)h1 << 32);
    lo = (unsigned long long)l0 | ((unsigned long long)l1 << 32);
}
__device__ __forceinline__ void sts64(uint32_t addr, unsigned long long v) {
    asm volatile("st.shared.b64 [%0], %1;" :: "r"(addr), "l"(v) : "memory");
}
__device__ __forceinline__ void cp16(uint32_t saddr, const void* g) {
    asm volatile("cp.async.cg.shared.global [%0], [%1], 16;"
                 :: "r"(saddr), "l"(g) : "memory");
}
#define CP_COMMIT() asm volatile("cp.async.commit_group;" ::: "memory")
#define CP_WAIT(n)  asm volatile("cp.async.wait_group %0;" :: "n"(n) : "memory")

__device__ __forceinline__ void ldsm_x4(uint32_t* r, uint32_t addr) {
    asm volatile("ldmatrix.sync.aligned.m8n8.x4.shared.b16 {%0,%1,%2,%3}, [%4];"
                 : "=r"(r[0]), "=r"(r[1]), "=r"(r[2]), "=r"(r[3]) : "r"(addr));
}
__device__ __forceinline__ void ldsm_x4_t(uint32_t* r, uint32_t addr) {
    asm volatile("ldmatrix.sync.aligned.m8n8.x4.trans.shared.b16 {%0,%1,%2,%3}, [%4];"
                 : "=r"(r[0]), "=r"(r[1]), "=r"(r[2]), "=r"(r[3]) : "r"(addr));
}
__device__ __forceinline__ void mma16816(float* d, const uint32_t* a,
                                         uint32_t b0, uint32_t b1) {
    asm volatile(
        "mma.sync.aligned.m16n8k16.row.col.f32.bf16.bf16.f32 "
        "{%0,%1,%2,%3}, {%4,%5,%6,%7}, {%8,%9}, {%0,%1,%2,%3};"
        : "+f"(d[0]), "+f"(d[1]), "+f"(d[2]), "+f"(d[3])
        : "r"(a[0]), "r"(a[1]), "r"(a[2]), "r"(a[3]), "r"(b0), "r"(b1));
}

// ---------------- prep 1: split enc_w and mem ----------------
__global__ void prep_split(const float* __restrict__ ew, const float* __restrict__ mm)
{
    int i = blockIdx.x * blockDim.x + threadIdx.x;
    int st = gridDim.x * blockDim.x;
    for (int j = i; j < DK * DIN; j += st) {
        float v = ew[j];
        __nv_bfloat16 h = __float2bfloat16_rn(v);
        g_encw_hi[j] = h;
        g_encw_lo[j] = __float2bfloat16_rn(v - __bfloat162float(h));
    }
    for (int j = i; j < MS * DK; j += st) {
        float v = mm[j];
        __nv_bfloat16 h = __float2bfloat16_rn(v);
        g_mem_hi[j] = h;
        g_mem_lo[j] = __float2bfloat16_rn(v - __bfloat162float(h));
    }
}

// ---------------- prep 2: Dt[s][n] = sum_k dec_w[n,k]*mem[s,k] ----------------
__global__ void prep_dt(const float* __restrict__ dw, const float* __restrict__ mm)
{
    int s = threadIdx.x & 63;
    int n = blockIdx.x * 4 + (threadIdx.x >> 6);
    const float4* wr = (const float4*)(dw + (size_t)n * DK);
    const float4* mr = (const float4*)(mm + (size_t)s * DK);
    float acc = 0.0f;
#pragma unroll 8
    for (int k = 0; k < DK / 4; k++) {
        float4 a = __ldg(wr + k), b = __ldg(mr + k);
        acc += a.x * b.x + a.y * b.y + a.z * b.z + a.w * b.w;
    }
    int idx = s * DIN + n;
    __nv_bfloat16 h = __float2bfloat16_rn(acc);
    g_dt_hi[idx] = h;
    g_dt_lo[idx] = __float2bfloat16_rn(acc - __bfloat162float(h));
}

// ===========================================================================
// Encode GEMM: 512 threads, 16 warps, warp tile 32x32. BM=BN=128, BK=32.
// ===========================================================================
#define RSB   80
#define PART  (128 * RSB)
#define BUFSZ (4 * PART)
#define GEMM_SMEM (2 * BUFSZ)

__global__ void __launch_bounds__(512, 1)
enc_gemm(const float* __restrict__ A32, const float* __restrict__ bias)
{
    extern __shared__ char smc[];
    const uint32_t sb = smem_u32(smc);
    const int tid = threadIdx.x, wid = tid >> 5, lane = tid & 31;
    const int wm = wid & 3, wn = wid >> 2;       // 4x4 warp grid, 32x32 tiles
    const int NCH = DIN / 32;                    // 16

    const size_t arow0 = (size_t)blockIdx.y * 128;
    const int n0 = blockIdx.x * 128;

    const int lrow = tid >> 3, lc4 = tid & 7;    // A: 2 float4/thread
    const int wrow = tid >> 2, wseg = tid & 3;   // W: 128r x 4seg, 1 cp16 hi+lo

    float acc[2][4][4];
#pragma unroll
    for (int i = 0; i < 2; i++)
#pragma unroll
        for (int j = 0; j < 4; j++)
#pragma unroll
            for (int k = 0; k < 4; k++) acc[i][j][k] = 0.0f;

    float4 av[2];

    auto issue_w = [&](int c, int buf) {
        const int k0 = c * 32;
        const uint32_t base = sb + buf * BUFSZ;
        uint32_t off = wrow * RSB + wseg * 16;
        cp16(base + 2 * PART + off,
             g_encw_hi + (size_t)(n0 + wrow) * DIN + k0 + wseg * 8);
        cp16(base + 3 * PART + off,
             g_encw_lo + (size_t)(n0 + wrow) * DIN + k0 + wseg * 8);
    };
    auto load_a = [&](int c) {
        const int k0 = c * 32;
#pragma unroll
        for (int l = 0; l < 2; l++) {
            int row = lrow + l * 64;
            av[l] = __ldg((const float4*)(A32 + (arow0 + row) * DIN + k0 + lc4 * 4));
        }
    };
    auto store_a = [&](int buf) {
        const uint32_t base = sb + buf * BUFSZ;
#pragma unroll
        for (int l = 0; l < 2; l++) {
            int row = lrow + l * 64;
            uint32_t off = row * RSB + lc4 * 8;
            unsigned long long hi, lo;
            split4(av[l], hi, lo);
            sts64(base + off, hi);
            sts64(base + PART + off, lo);
        }
    };
    auto compute = [&](int buf) {
        const uint32_t base = sb + buf * BUFSZ;
        const uint32_t lr = lane & 15, lh = (lane >> 4) * 16;
#pragma unroll
        for (int ks = 0; ks < 2; ks++) {
            uint32_t ahf[2][4], alf[2][4], whf[2][4], wlf[2][4];
#pragma unroll
            for (int mt = 0; mt < 2; mt++) {
                uint32_t ao = (wm * 32 + mt * 16 + lr) * RSB + ks * 32 + lh;
                ldsm_x4(ahf[mt], base + ao);
                ldsm_x4(alf[mt], base + PART + ao);
            }
#pragma unroll
            for (int g = 0; g < 2; g++) {
                uint32_t wo = (wn * 32 + g * 16 + lr) * RSB + ks * 32 + lh;
                ldsm_x4(whf[g], base + 2 * PART + wo);
                ldsm_x4(wlf[g], base + 3 * PART + wo);
            }
#pragma unroll
            for (int mt = 0; mt < 2; mt++)
#pragma unroll
                for (int g = 0; g < 2; g++) {
                    mma16816(acc[mt][2 * g],     ahf[mt], whf[g][0], whf[g][2]);
                    mma16816(acc[mt][2 * g + 1], ahf[mt], whf[g][1], whf[g][3]);
                }
#pragma unroll
            for (int mt = 0; mt < 2; mt++)
#pragma unroll
                for (int g = 0; g < 2; g++) {
                    mma16816(acc[mt][2 * g],     ahf[mt], wlf[g][0], wlf[g][2]);
                    mma16816(acc[mt][2 * g + 1], ahf[mt], wlf[g][1], wlf[g][3]);
                }
#pragma unroll
            for (int mt = 0; mt < 2; mt++)
#pragma unroll
                for (int g = 0; g < 2; g++) {
                    mma16816(acc[mt][2 * g],     alf[mt], whf[g][0], whf[g][2]);
                    mma16816(acc[mt][2 * g + 1], alf[mt], whf[g][1], whf[g][3]);
                }
        }
    };

    // prologue
    issue_w(0, 0); CP_COMMIT();
    load_a(0); store_a(0);

    for (int c = 0; c < NCH; c++) {
        CP_WAIT(0);
        __syncthreads();                  // chunk c ready; old buf retired
        if (c + 1 < NCH) {
            issue_w(c + 1, (c + 1) & 1); CP_COMMIT();
            load_a(c + 1);
        }
        compute(c & 1);
        if (c + 1 < NCH) store_a((c + 1) & 1);
    }

    // epilogue: tanh -> bf16 hi/lo
    const int tq = lane >> 2, tr = lane & 3;
#pragma unroll
    for (int mt = 0; mt < 2; mt++) {
        size_t r0 = arow0 + wm * 32 + mt * 16 + tq;
#pragma unroll
        for (int nt = 0; nt < 4; nt++) {
            int gn = n0 + wn * 32 + nt * 8 + tr * 2;
            float bx = bias[gn], by = bias[gn + 1];
            float v0 = tanhf(acc[mt][nt][0] + bx), v1 = tanhf(acc[mt][nt][1] + by);
            float v2 = tanhf(acc[mt][nt][2] + bx), v3 = tanhf(acc[mt][nt][3] + by);
            uint32_t h, l;
            split2(v0, v1, h, l);
            *(uint32_t*)(g_enc_hi + r0 * DK + gn) = h;
            *(uint32_t*)(g_enc_lo + r0 * DK + gn) = l;
            split2(v2, v3, h, l);
            *(uint32_t*)(g_enc_hi + (r0 + 8) * DK + gn) = h;
            *(uint32_t*)(g_enc_lo + (r0 + 8) * DK + gn) = l;
        }
    }
}

// ===========================================================================
// Fused attention + decode: 256 tokens/block, 512 threads (16 warps x 16 tok).
// E consumed in 4 K-chunks (double-buffered). mem resident. Dt overlays E.
// ===========================================================================
#define EROW   528                 // mem row: 256 bf16 + pad
#define ECROW  144                 // E chunk row: 64 bf16 + pad
#define DTROW  1040                // Dt row: 512 bf16 + pad
#define MEMSZ  (2 * 64 * EROW)     // 67584
#define ECBUF  (2 * 256 * ECROW)   // 73728 (hi then lo)
#define AT_SMEM (MEMSZ + 2 * ECBUF)   // 215040

__global__ void __launch_bounds__(512, 1)
attn_fused(float* __restrict__ att_out, float* __restrict__ mem_out,
           float* __restrict__ recon, const float* __restrict__ dec_b)
{
    extern __shared__ char smc[];
    const uint32_t sb = smem_u32(smc);
    const uint32_t sMhi = sb, sMlo = sb + 64 * EROW;
    const uint32_t sE0 = sb + MEMSZ;                  // 2 chunk buffers
    const uint32_t sDhi = sE0, sDlo = sE0 + 64 * DTROW;   // overlay after logits

    const int tid = threadIdx.x, wid = tid >> 5, lane = tid & 31;
    const size_t t0 = (size_t)blockIdx.x * 256;

    auto issue_mem = [&]() {
#pragma unroll
        for (int it = 0; it < 4; it++) {
            int idx = tid + it * 512;
            int row = idx >> 5, c = idx & 31;
            cp16(sMhi + row * EROW + c * 16, g_mem_hi + row * DK + c * 8);
            cp16(sMlo + row * EROW + c * 16, g_mem_lo + row * DK + c * 8);
        }
    };
    auto issue_e = [&](int kc, int buf) {
        const uint32_t base = sE0 + buf * ECBUF;
#pragma unroll
        for (int it = 0; it < 4; it++) {
            int idx = tid + it * 512;
            int row = idx >> 3, seg = idx & 7;
            const size_t go = (t0 + row) * DK + kc * 64 + seg * 8;
            cp16(base + row * ECROW + seg * 16, g_enc_hi + go);
            cp16(base + 256 * ECROW + row * ECROW + seg * 16, g_enc_lo + go);
        }
    };

    issue_mem();
    issue_e(0, 0);
    CP_COMMIT();

    const int lr = lane & 15, half = lane >> 4;
    const int tq = lane >> 2, tr = lane & 3;
    const int r0 = wid * 16;

    float S[8][4];
#pragma unroll
    for (int i = 0; i < 8; i++)
#pragma unroll
        for (int j = 0; j < 4; j++) S[i][j] = 0.0f;

    for (int kc = 0; kc < 4; kc++) {
        CP_WAIT(0);
        __syncthreads();
        if (kc < 4 - 1) { issue_e(kc + 1, (kc + 1) & 1); CP_COMMIT(); }
        const uint32_t eb = sE0 + (kc & 1) * ECBUF;
#pragma unroll
        for (int ks = 0; ks < 4; ks++) {
            uint32_t aoff = (r0 + lr) * ECROW + ks * 32 + half * 16;
            uint32_t ahf[4], alf[4], bh[4][4], bl[4][4];
            ldsm_x4(ahf, eb + aoff);
            ldsm_x4(alf, eb + 256 * ECROW + aoff);
            const int kbyte = (kc * 4 + ks) * 32 + half * 16;
#pragma unroll
            for (int g = 0; g < 4; g++) {
                uint32_t woff = (g * 16 + lr) * EROW + kbyte;
                ldsm_x4(bh[g], sMhi + woff);
                ldsm_x4(bl[g], sMlo + woff);
            }
#pragma unroll
            for (int g = 0; g < 4; g++) {
                mma16816(S[2 * g],     ahf, bh[g][0], bh[g][2]);
                mma16816(S[2 * g + 1], ahf, bh[g][1], bh[g][3]);
            }
#pragma unroll
            for (int g = 0; g < 4; g++) {
                mma16816(S[2 * g],     ahf, bl[g][0], bl[g][2]);
                mma16816(S[2 * g + 1], ahf, bl[g][1], bl[g][3]);
            }
#pragma unroll
            for (int g = 0; g < 4; g++) {
                mma16816(S[2 * g],     alf, bh[g][0], bh[g][2]);
                mma16816(S[2 * g + 1], alf, bh[g][1], bh[g][3]);
            }
        }
    }

    __syncthreads();     // all warps done with E buffers

    // prefetch Dt into dead E region (overlaps softmax + att + memo)
#pragma unroll
    for (int it = 0; it < 8; it++) {
        int idx = tid + it * 512;
        int row = idx >> 6, c = idx & 63;
        cp16(sDhi + row * DTROW + c * 16, g_dt_hi + row * DIN + c * 8);
        cp16(sDlo + row * DTROW + c * 16, g_dt_lo + row * DIN + c * 8);
    }
    CP_COMMIT();

    // ---- softmax (register-only) ----
    float m0 = -1e30f, m1 = -1e30f;
#pragma unroll
    for (int nt = 0; nt < 8; nt++) {
        m0 = fmaxf(m0, fmaxf(S[nt][0], S[nt][1]));
        m1 = fmaxf(m1, fmaxf(S[nt][2], S[nt][3]));
    }
    m0 = fmaxf(m0, __shfl_xor_sync(0xffffffffu, m0, 1));
    m0 = fmaxf(m0, __shfl_xor_sync(0xffffffffu, m0, 2));
    m1 = fmaxf(m1, __shfl_xor_sync(0xffffffffu, m1, 1));
    m1 = fmaxf(m1, __shfl_xor_sync(0xffffffffu, m1, 2));
    float s0 = 0.0f, s1 = 0.0f;
#pragma unroll
    for (int nt = 0; nt < 8; nt++) {
        S[nt][0] = expf((S[nt][0] - m0) * 0.0625f); s0 += S[nt][0];
        S[nt][1] = expf((S[nt][1] - m0) * 0.0625f); s0 += S[nt][1];
        S[nt][2] = expf((S[nt][2] - m1) * 0.0625f); s1 += S[nt][2];
        S[nt][3] = expf((S[nt][3] - m1) * 0.0625f); s1 += S[nt][3];
    }
    s0 += __shfl_xor_sync(0xffffffffu, s0, 1);
    s0 += __shfl_xor_sync(0xffffffffu, s0, 2);
    s1 += __shfl_xor_sync(0xffffffffu, s1, 1);
    s1 += __shfl_xor_sync(0xffffffffu, s1, 2);
    float i0 = 1.0f / s0, i1 = 1.0f / s1;
#pragma unroll
    for (int nt = 0; nt < 8; nt++) {
        S[nt][0] *= i0; S[nt][1] *= i0; S[nt][2] *= i1; S[nt][3] *= i1;
    }

    // repack P into A-fragments
    uint32_t Ph[4][4], Pl[4][4];
#pragma unroll
    for (int kt = 0; kt < 4; kt++) {
        split2(S[2 * kt][0],     S[2 * kt][1],     Ph[kt][0], Pl[kt][0]);
        split2(S[2 * kt][2],     S[2 * kt][3],     Ph[kt][1], Pl[kt][1]);
        split2(S[2 * kt + 1][0], S[2 * kt + 1][1], Ph[kt][2], Pl[kt][2]);
        split2(S[2 * kt + 1][2], S[2 * kt + 1][3], Ph[kt][3], Pl[kt][3]);
    }

    // attention output
    const size_t ra = t0 + r0 + tq;
#pragma unroll
    for (int nt = 0; nt < 8; nt++) {
        float2 o0, o1;
        o0.x = S[nt][0]; o0.y = S[nt][1];
        o1.x = S[nt][2]; o1.y = S[nt][3];
        *(float2*)(att_out + ra * MS + nt * 8 + tr * 2)       = o0;
        *(float2*)(att_out + (ra + 8) * MS + nt * 8 + tr * 2) = o1;
    }

    // ---- memo = P @ mem ----
    const int lr8 = lane & 7, kh = (lane >> 3) & 1, nh = lane >> 4;
#pragma unroll
    for (int nc = 0; nc < 4; nc++) {
        float acc2[8][4];
#pragma unroll
        for (int i = 0; i < 8; i++)
#pragma unroll
            for (int j = 0; j < 4; j++) acc2[i][j] = 0.0f;
#pragma unroll
        for (int kt = 0; kt < 4; kt++) {
            uint32_t bh[4][4], bl[4][4];
#pragma unroll
            for (int g2 = 0; g2 < 4; g2++) {
                uint32_t boff = (uint32_t)(kt * 16 + kh * 8 + lr8) * EROW +
                                (nc * 64 + g2 * 16 + nh * 8) * 2;
                ldsm_x4_t(bh[g2], sMhi + boff);
                ldsm_x4_t(bl[g2], sMlo + boff);
            }
#pragma unroll
            for (int g2 = 0; g2 < 4; g2++) {
                mma16816(acc2[2 * g2],     Ph[kt], bh[g2][0], bh[g2][1]);
                mma16816(acc2[2 * g2 + 1], Ph[kt], bh[g2][2], bh[g2][3]);
            }
#pragma unroll
            for (int g2 = 0; g2 < 4; g2++) {
                mma16816(acc2[2 * g2],     Ph[kt], bl[g2][0], bl[g2][1]);
                mma16816(acc2[2 * g2 + 1], Ph[kt], bl[g2][2], bl[g2][3]);
            }
#pragma unroll
            for (int g2 = 0; g2 < 4; g2++) {
                mma16816(acc2[2 * g2],     Pl[kt], bh[g2][0], bh[g2][1]);
                mma16816(acc2[2 * g2 + 1], Pl[kt], bh[g2][2], bh[g2][3]);
            }
        }
#pragma unroll
        for (int nt2 = 0; nt2 < 8; nt2++) {
            int gc = nc * 64 + nt2 * 8 + tr * 2;
            float2 o0, o1;
            o0.x = acc2[nt2][0]; o0.y = acc2[nt2][1];
            o1.x = acc2[nt2][2]; o1.y = acc2[nt2][3];
            *(float2*)(mem_out + ra * DK + gc)       = o0;
            *(float2*)(mem_out + (ra + 8) * DK + gc) = o1;
        }
    }

    CP_WAIT(0);
    __syncthreads();     // Dt visible

    // ---- recon = P @ Dt + dec_b ----
#pragma unroll
    for (int nc = 0; nc < 8; nc++) {
        float acc2[8][4];
#pragma unroll
        for (int i = 0; i < 8; i++)
#pragma unroll
            for (int j = 0; j < 4; j++) acc2[i][j] = 0.0f;
#pragma unroll
        for (int kt = 0; kt < 4; kt++) {
            uint32_t bh[4][4], bl[4][4];
#pragma unroll
            for (int g2 = 0; g2 < 4; g2++) {
                uint32_t boff = (uint32_t)(kt * 16 + kh * 8 + lr8) * DTROW +
                                (nc * 64 + g2 * 16 + nh * 8) * 2;
                ldsm_x4_t(bh[g2], sDhi + boff);
                ldsm_x4_t(bl[g2], sDlo + boff);
            }
#pragma unroll
            for (int g2 = 0; g2 < 4; g2++) {
                mma16816(acc2[2 * g2],     Ph[kt], bh[g2][0], bh[g2][1]);
                mma16816(acc2[2 * g2 + 1], Ph[kt], bh[g2][2], bh[g2][3]);
            }
#pragma unroll
            for (int g2 = 0; g2 < 4; g2++) {
                mma16816(acc2[2 * g2],     Ph[kt], bl[g2][0], bl[g2][1]);
                mma16816(acc2[2 * g2 + 1], Ph[kt], bl[g2][2], bl[g2][3]);
            }
#pragma unroll
            for (int g2 = 0; g2 < 4; g2++) {
                mma16816(acc2[2 * g2],     Pl[kt], bh[g2][0], bh[g2][1]);
                mma16816(acc2[2 * g2 + 1], Pl[kt], bh[g2][2], bh[g2][3]);
            }
        }
#pragma unroll
        for (int nt2 = 0; nt2 < 8; nt2++) {
            int gc = nc * 64 + nt2 * 8 + tr * 2;
            float2 b2 = *(const float2*)(dec_b + gc);
            float2 o0, o1;
            o0.x = acc2[nt2][0] + b2.x; o0.y = acc2[nt2][1] + b2.y;
            o1.x = acc2[nt2][2] + b2.x; o1.y = acc2[nt2][3] + b2.y;
            *(float2*)(recon + ra * DIN + gc)       = o0;
            *(float2*)(recon + (ra + 8) * DIN + gc) = o1;
        }
    }
}

// ---------------------------------------------------------------------------
extern "C" void kernel_launch(void* const* d_in, const int* in_sizes, int n_in,
                              void* d_out, int out_size)
{
    const float* seq   = (const float*)d_in[0];
    const float* enc_w = (const float*)d_in[1];
    const float* enc_b = (const float*)d_in[2];
    const float* mem   = (const float*)d_in[3];
    const float* dec_w = (const float*)d_in[4];
    const float* dec_b = (const float*)d_in[5];

    float* recon = (float*)d_out;
    float* att   = recon + (size_t)NTOK * DIN;
    float* memo  = att   + (size_t)NTOK * MS;

    cudaFuncSetAttribute(enc_gemm,
                         cudaFuncAttributeMaxDynamicSharedMemorySize, GEMM_SMEM);
    cudaFuncSetAttribute(attn_fused,
                         cudaFuncAttributeMaxDynamicSharedMemorySize, AT_SMEM);

    prep_split<<<160, 256>>>(enc_w, mem);
    prep_dt<<<DIN / 4, 256>>>(dec_w, mem);

    dim3 g1(DK / 128, NTOK / 128);
    enc_gemm<<<g1, 512, GEMM_SMEM>>>(seq, enc_b);

    attn_fused<<<NTOK / 256, 512, AT_SMEM>>>(att, memo, recon, dec_b);
}

// round 9
// speedup vs baseline: 4.5628x; 1.2844x over previous
#include <cuda_runtime.h>
#include <cuda_fp16.h>
#include <cstdint>
#include <math.h>

#define NTOK  65536
#define DIN   512
#define DK    256
#define MS    64

// ---------------- static scratch (fp16) ----------------
__device__ __half g_encw_h[DK * DIN];                      // enc_w single fp16
__device__ __half g_mem_h[MS * DK];                        // mem single fp16
__device__ __half g_dt_h[MS * DIN];                        // Dt single fp16
__device__ __half g_enc_hi[(size_t)NTOK * DK], g_enc_lo[(size_t)NTOK * DK];

// ======================= helpers =======================
__device__ __forceinline__ uint32_t smem_u32(const void* p) {
    uint32_t a;
    asm("{ .reg .u64 t; cvta.to.shared.u64 t, %1; cvt.u32.u64 %0, t; }"
        : "=r"(a) : "l"(p));
    return a;
}
__device__ __forceinline__ uint32_t pack_h2(float a, float b) {
    __half2 t = __floats2half2_rn(a, b);
    return *reinterpret_cast<uint32_t*>(&t);
}
__device__ __forceinline__ void split2h(float a, float b, uint32_t& hi, uint32_t& lo) {
    __half ha = __float2half_rn(a), hb = __float2half_rn(b);
    __half2 hp; hp.x = ha; hp.y = hb;
    hi = *reinterpret_cast<uint32_t*>(&hp);
    lo = pack_h2(a - __half2float(ha), b - __half2float(hb));
}
__device__ __forceinline__ void split4h(float4 v, unsigned long long& hi,
                                        unsigned long long& lo) {
    uint32_t h0, l0, h1, l1;
    split2h(v.x, v.y, h0, l0);
    split2h(v.z, v.w, h1, l1);
    hi = (unsigned long long)h0 | ((unsigned long long)h1 << 32);
    lo = (unsigned long long)l0 | ((unsigned long long)l1 << 32);
}
__device__ __forceinline__ void sts64(uint32_t addr, unsigned long long v) {
    asm volatile("st.shared.b64 [%0], %1;" :: "r"(addr), "l"(v) : "memory");
}
__device__ __forceinline__ void cp16(uint32_t saddr, const void* g) {
    asm volatile("cp.async.cg.shared.global [%0], [%1], 16;"
                 :: "r"(saddr), "l"(g) : "memory");
}
#define CP_COMMIT() asm volatile("cp.async.commit_group;" ::: "memory")
#define CP_WAIT(n)  asm volatile("cp.async.wait_group %0;" :: "n"(n) : "memory")

__device__ __forceinline__ void ldsm_x4(uint32_t* r, uint32_t addr) {
    asm volatile("ldmatrix.sync.aligned.m8n8.x4.shared.b16 {%0,%1,%2,%3}, [%4];"
                 : "=r"(r[0]), "=r"(r[1]), "=r"(r[2]), "=r"(r[3]) : "r"(addr));
}
__device__ __forceinline__ void ldsm_x4_t(uint32_t* r, uint32_t addr) {
    asm volatile("ldmatrix.sync.aligned.m8n8.x4.trans.shared.b16 {%0,%1,%2,%3}, [%4];"
                 : "=r"(r[0]), "=r"(r[1]), "=r"(r[2]), "=r"(r[3]) : "r"(addr));
}
__device__ __forceinline__ void mma16816(float* d, const uint32_t* a,
                                         uint32_t b0, uint32_t b1) {
    asm volatile(
        "mma.sync.aligned.m16n8k16.row.col.f32.f16.f16.f32 "
        "{%0,%1,%2,%3}, {%4,%5,%6,%7}, {%8,%9}, {%0,%1,%2,%3};"
        : "+f"(d[0]), "+f"(d[1]), "+f"(d[2]), "+f"(d[3])
        : "r"(a[0]), "r"(a[1]), "r"(a[2]), "r"(a[3]), "r"(b0), "r"(b1));
}

// ---------------- prep 1: enc_w, mem -> fp16 ----------------
__global__ void prep_cvt(const float* __restrict__ ew, const float* __restrict__ mm)
{
    int i = blockIdx.x * blockDim.x + threadIdx.x;
    int st = gridDim.x * blockDim.x;
    for (int j = i; j < DK * DIN; j += st)
        g_encw_h[j] = __float2half_rn(ew[j]);
    for (int j = i; j < MS * DK; j += st)
        g_mem_h[j] = __float2half_rn(mm[j]);
}

// ---------------- prep 2: Dt[s][n] = dec_w[n,:].mem[s,:] -> fp16 ----------------
__global__ void prep_dt(const float* __restrict__ dw, const float* __restrict__ mm)
{
    int s = threadIdx.x & 63;
    int n = blockIdx.x * 4 + (threadIdx.x >> 6);
    const float4* wr = (const float4*)(dw + (size_t)n * DK);
    const float4* mr = (const float4*)(mm + (size_t)s * DK);
    float acc = 0.0f;
#pragma unroll 8
    for (int k = 0; k < DK / 4; k++) {
        float4 a = __ldg(wr + k), b = __ldg(mr + k);
        acc += a.x * b.x + a.y * b.y + a.z * b.z + a.w * b.w;
    }
    g_dt_h[s * DIN + n] = __float2half_rn(acc);
}

// ===========================================================================
// Encode GEMM: 512 threads, 16 warps, warp tile 32x32. BM=BN=128, BK=32.
// A split fp16 hi/lo in-kernel; W single fp16 via cp.async. 2-pass MMA.
// ===========================================================================
#define RSB   80
#define PART  (128 * RSB)          // 10240
#define BUFSZ (3 * PART)           // Ahi | Alo | W
#define GEMM_SMEM (2 * BUFSZ)      // 61440

__global__ void __launch_bounds__(512, 1)
enc_gemm(const float* __restrict__ A32, const float* __restrict__ bias)
{
    extern __shared__ char smc[];
    const uint32_t sb = smem_u32(smc);
    const int tid = threadIdx.x, wid = tid >> 5, lane = tid & 31;
    const int wm = wid & 3, wn = wid >> 2;
    const int NCH = DIN / 32;                    // 16

    const size_t arow0 = (size_t)blockIdx.y * 128;
    const int n0 = blockIdx.x * 128;

    const int lrow = tid >> 3, lc4 = tid & 7;
    const int wrow = tid >> 2, wseg = tid & 3;

    float acc[2][4][4];
#pragma unroll
    for (int i = 0; i < 2; i++)
#pragma unroll
        for (int j = 0; j < 4; j++)
#pragma unroll
            for (int k = 0; k < 4; k++) acc[i][j][k] = 0.0f;

    float4 av[2];

    auto issue_w = [&](int c, int buf) {
        const int k0 = c * 32;
        const uint32_t base = sb + buf * BUFSZ;
        cp16(base + 2 * PART + wrow * RSB + wseg * 16,
             g_encw_h + (size_t)(n0 + wrow) * DIN + k0 + wseg * 8);
    };
    auto load_a = [&](int c) {
        const int k0 = c * 32;
#pragma unroll
        for (int l = 0; l < 2; l++) {
            int row = lrow + l * 64;
            av[l] = __ldg((const float4*)(A32 + (arow0 + row) * DIN + k0 + lc4 * 4));
        }
    };
    auto store_a = [&](int buf) {
        const uint32_t base = sb + buf * BUFSZ;
#pragma unroll
        for (int l = 0; l < 2; l++) {
            int row = lrow + l * 64;
            uint32_t off = row * RSB + lc4 * 8;
            unsigned long long hi, lo;
            split4h(av[l], hi, lo);
            sts64(base + off, hi);
            sts64(base + PART + off, lo);
        }
    };
    auto compute = [&](int buf) {
        const uint32_t base = sb + buf * BUFSZ;
        const uint32_t lr = lane & 15, lh = (lane >> 4) * 16;
#pragma unroll
        for (int ks = 0; ks < 2; ks++) {
            uint32_t ahf[2][4], alf[2][4], whf[2][4];
#pragma unroll
            for (int mt = 0; mt < 2; mt++) {
                uint32_t ao = (wm * 32 + mt * 16 + lr) * RSB + ks * 32 + lh;
                ldsm_x4(ahf[mt], base + ao);
                ldsm_x4(alf[mt], base + PART + ao);
            }
#pragma unroll
            for (int g = 0; g < 2; g++) {
                uint32_t wo = (wn * 32 + g * 16 + lr) * RSB + ks * 32 + lh;
                ldsm_x4(whf[g], base + 2 * PART + wo);
            }
            // pass 1: A_hi x W
#pragma unroll
            for (int mt = 0; mt < 2; mt++)
#pragma unroll
                for (int g = 0; g < 2; g++) {
                    mma16816(acc[mt][2 * g],     ahf[mt], whf[g][0], whf[g][2]);
                    mma16816(acc[mt][2 * g + 1], ahf[mt], whf[g][1], whf[g][3]);
                }
            // pass 2: A_lo x W
#pragma unroll
            for (int mt = 0; mt < 2; mt++)
#pragma unroll
                for (int g = 0; g < 2; g++) {
                    mma16816(acc[mt][2 * g],     alf[mt], whf[g][0], whf[g][2]);
                    mma16816(acc[mt][2 * g + 1], alf[mt], whf[g][1], whf[g][3]);
                }
        }
    };

    issue_w(0, 0); CP_COMMIT();
    load_a(0); store_a(0);

    for (int c = 0; c < NCH; c++) {
        CP_WAIT(0);
        __syncthreads();
        if (c + 1 < NCH) {
            issue_w(c + 1, (c + 1) & 1); CP_COMMIT();
            load_a(c + 1);
        }
        compute(c & 1);
        if (c + 1 < NCH) store_a((c + 1) & 1);
    }

    // epilogue: tanh -> fp16 hi/lo
    const int tq = lane >> 2, tr = lane & 3;
#pragma unroll
    for (int mt = 0; mt < 2; mt++) {
        size_t r0 = arow0 + wm * 32 + mt * 16 + tq;
#pragma unroll
        for (int nt = 0; nt < 4; nt++) {
            int gn = n0 + wn * 32 + nt * 8 + tr * 2;
            float bx = bias[gn], by = bias[gn + 1];
            float v0 = tanhf(acc[mt][nt][0] + bx), v1 = tanhf(acc[mt][nt][1] + by);
            float v2 = tanhf(acc[mt][nt][2] + bx), v3 = tanhf(acc[mt][nt][3] + by);
            uint32_t h, l;
            split2h(v0, v1, h, l);
            *(uint32_t*)(g_enc_hi + r0 * DK + gn) = h;
            *(uint32_t*)(g_enc_lo + r0 * DK + gn) = l;
            split2h(v2, v3, h, l);
            *(uint32_t*)(g_enc_hi + (r0 + 8) * DK + gn) = h;
            *(uint32_t*)(g_enc_lo + (r0 + 8) * DK + gn) = l;
        }
    }
}

// ===========================================================================
// Fused attention + decode: 256 tokens/block, 512 threads. 2-pass fp16.
// mem + Dt single fp16; E and P fp16 hi/lo.
// ===========================================================================
#define EROW   528                 // mem row: 256 fp16 + pad
#define ECROW  144                 // E chunk row: 64 fp16 + pad
#define DTROW  1040                // Dt row: 512 fp16 + pad
#define MEMSZ  (64 * EROW)         // 33792 (single plane)
#define ECBUF  (2 * 256 * ECROW)   // 73728 (hi+lo)
#define AT_SMEM (MEMSZ + 2 * ECBUF)   // 181248

__global__ void __launch_bounds__(512, 1)
attn_fused(float* __restrict__ att_out, float* __restrict__ mem_out,
           float* __restrict__ recon, const float* __restrict__ dec_b)
{
    extern __shared__ char smc[];
    const uint32_t sb = smem_u32(smc);
    const uint32_t sM = sb;
    const uint32_t sE0 = sb + MEMSZ;
    const uint32_t sD = sE0;                       // Dt overlays E after logits

    const int tid = threadIdx.x, wid = tid >> 5, lane = tid & 31;
    const size_t t0 = (size_t)blockIdx.x * 256;

    auto issue_mem = [&]() {
#pragma unroll
        for (int it = 0; it < 4; it++) {
            int idx = tid + it * 512;
            int row = idx >> 5, c = idx & 31;
            cp16(sM + row * EROW + c * 16, g_mem_h + row * DK + c * 8);
        }
    };
    auto issue_e = [&](int kc, int buf) {
        const uint32_t base = sE0 + buf * ECBUF;
#pragma unroll
        for (int it = 0; it < 4; it++) {
            int idx = tid + it * 512;
            int row = idx >> 3, seg = idx & 7;
            const size_t go = (t0 + row) * DK + kc * 64 + seg * 8;
            cp16(base + row * ECROW + seg * 16, g_enc_hi + go);
            cp16(base + 256 * ECROW + row * ECROW + seg * 16, g_enc_lo + go);
        }
    };

    issue_mem();
    issue_e(0, 0);
    CP_COMMIT();

    const int lr = lane & 15, half = lane >> 4;
    const int tq = lane >> 2, tr = lane & 3;
    const int r0 = wid * 16;

    float S[8][4];
#pragma unroll
    for (int i = 0; i < 8; i++)
#pragma unroll
        for (int j = 0; j < 4; j++) S[i][j] = 0.0f;

    for (int kc = 0; kc < 4; kc++) {
        CP_WAIT(0);
        __syncthreads();
        if (kc < 3) { issue_e(kc + 1, (kc + 1) & 1); CP_COMMIT(); }
        const uint32_t eb = sE0 + (kc & 1) * ECBUF;
#pragma unroll
        for (int ks = 0; ks < 4; ks++) {
            uint32_t aoff = (r0 + lr) * ECROW + ks * 32 + half * 16;
            uint32_t ahf[4], alf[4], bh[4][4];
            ldsm_x4(ahf, eb + aoff);
            ldsm_x4(alf, eb + 256 * ECROW + aoff);
            const int kbyte = (kc * 4 + ks) * 32 + half * 16;
#pragma unroll
            for (int g = 0; g < 4; g++)
                ldsm_x4(bh[g], sM + (g * 16 + lr) * EROW + kbyte);
#pragma unroll
            for (int g = 0; g < 4; g++) {
                mma16816(S[2 * g],     ahf, bh[g][0], bh[g][2]);
                mma16816(S[2 * g + 1], ahf, bh[g][1], bh[g][3]);
            }
#pragma unroll
            for (int g = 0; g < 4; g++) {
                mma16816(S[2 * g],     alf, bh[g][0], bh[g][2]);
                mma16816(S[2 * g + 1], alf, bh[g][1], bh[g][3]);
            }
        }
    }

    __syncthreads();     // all warps done with E buffers

    // prefetch Dt into dead E region
#pragma unroll
    for (int it = 0; it < 8; it++) {
        int idx = tid + it * 512;
        int row = idx >> 6, c = idx & 63;
        cp16(sD + row * DTROW + c * 16, g_dt_h + row * DIN + c * 8);
    }
    CP_COMMIT();

    // ---- softmax (register-only) ----
    float m0 = -1e30f, m1 = -1e30f;
#pragma unroll
    for (int nt = 0; nt < 8; nt++) {
        m0 = fmaxf(m0, fmaxf(S[nt][0], S[nt][1]));
        m1 = fmaxf(m1, fmaxf(S[nt][2], S[nt][3]));
    }
    m0 = fmaxf(m0, __shfl_xor_sync(0xffffffffu, m0, 1));
    m0 = fmaxf(m0, __shfl_xor_sync(0xffffffffu, m0, 2));
    m1 = fmaxf(m1, __shfl_xor_sync(0xffffffffu, m1, 1));
    m1 = fmaxf(m1, __shfl_xor_sync(0xffffffffu, m1, 2));
    float s0 = 0.0f, s1 = 0.0f;
#pragma unroll
    for (int nt = 0; nt < 8; nt++) {
        S[nt][0] = expf((S[nt][0] - m0) * 0.0625f); s0 += S[nt][0];
        S[nt][1] = expf((S[nt][1] - m0) * 0.0625f); s0 += S[nt][1];
        S[nt][2] = expf((S[nt][2] - m1) * 0.0625f); s1 += S[nt][2];
        S[nt][3] = expf((S[nt][3] - m1) * 0.0625f); s1 += S[nt][3];
    }
    s0 += __shfl_xor_sync(0xffffffffu, s0, 1);
    s0 += __shfl_xor_sync(0xffffffffu, s0, 2);
    s1 += __shfl_xor_sync(0xffffffffu, s1, 1);
    s1 += __shfl_xor_sync(0xffffffffu, s1, 2);
    float i0 = 1.0f / s0, i1 = 1.0f / s1;
#pragma unroll
    for (int nt = 0; nt < 8; nt++) {
        S[nt][0] *= i0; S[nt][1] *= i0; S[nt][2] *= i1; S[nt][3] *= i1;
    }

    // repack P into fp16 A-fragments (hi/lo)
    uint32_t Ph[4][4], Pl[4][4];
#pragma unroll
    for (int kt = 0; kt < 4; kt++) {
        split2h(S[2 * kt][0],     S[2 * kt][1],     Ph[kt][0], Pl[kt][0]);
        split2h(S[2 * kt][2],     S[2 * kt][3],     Ph[kt][1], Pl[kt][1]);
        split2h(S[2 * kt + 1][0], S[2 * kt + 1][1], Ph[kt][2], Pl[kt][2]);
        split2h(S[2 * kt + 1][2], S[2 * kt + 1][3], Ph[kt][3], Pl[kt][3]);
    }

    // attention output
    const size_t ra = t0 + r0 + tq;
#pragma unroll
    for (int nt = 0; nt < 8; nt++) {
        float2 o0, o1;
        o0.x = S[nt][0]; o0.y = S[nt][1];
        o1.x = S[nt][2]; o1.y = S[nt][3];
        *(float2*)(att_out + ra * MS + nt * 8 + tr * 2)       = o0;
        *(float2*)(att_out + (ra + 8) * MS + nt * 8 + tr * 2) = o1;
    }

    // ---- memo = P @ mem (2-pass) ----
    const int lr8 = lane & 7, kh = (lane >> 3) & 1, nh = lane >> 4;
#pragma unroll
    for (int nc = 0; nc < 4; nc++) {
        float acc2[8][4];
#pragma unroll
        for (int i = 0; i < 8; i++)
#pragma unroll
            for (int j = 0; j < 4; j++) acc2[i][j] = 0.0f;
#pragma unroll
        for (int kt = 0; kt < 4; kt++) {
            uint32_t bh[4][4];
#pragma unroll
            for (int g2 = 0; g2 < 4; g2++) {
                uint32_t boff = (uint32_t)(kt * 16 + kh * 8 + lr8) * EROW +
                                (nc * 64 + g2 * 16 + nh * 8) * 2;
                ldsm_x4_t(bh[g2], sM + boff);
            }
#pragma unroll
            for (int g2 = 0; g2 < 4; g2++) {
                mma16816(acc2[2 * g2],     Ph[kt], bh[g2][0], bh[g2][1]);
                mma16816(acc2[2 * g2 + 1], Ph[kt], bh[g2][2], bh[g2][3]);
            }
#pragma unroll
            for (int g2 = 0; g2 < 4; g2++) {
                mma16816(acc2[2 * g2],     Pl[kt], bh[g2][0], bh[g2][1]);
                mma16816(acc2[2 * g2 + 1], Pl[kt], bh[g2][2], bh[g2][3]);
            }
        }
#pragma unroll
        for (int nt2 = 0; nt2 < 8; nt2++) {
            int gc = nc * 64 + nt2 * 8 + tr * 2;
            float2 o0, o1;
            o0.x = acc2[nt2][0]; o0.y = acc2[nt2][1];
            o1.x = acc2[nt2][2]; o1.y = acc2[nt2][3];
            *(float2*)(mem_out + ra * DK + gc)       = o0;
            *(float2*)(mem_out + (ra + 8) * DK + gc) = o1;
        }
    }

    CP_WAIT(0);
    __syncthreads();     // Dt visible

    // ---- recon = P @ Dt + dec_b (2-pass) ----
#pragma unroll
    for (int nc = 0; nc < 8; nc++) {
        float acc2[8][4];
#pragma unroll
        for (int i = 0; i < 8; i++)
#pragma unroll
            for (int j = 0; j < 4; j++) acc2[i][j] = 0.0f;
#pragma unroll
        for (int kt = 0; kt < 4; kt++) {
            uint32_t bh[4][4];
#pragma unroll
            for (int g2 = 0; g2 < 4; g2++) {
                uint32_t boff = (uint32_t)(kt * 16 + kh * 8 + lr8) * DTROW +
                                (nc * 64 + g2 * 16 + nh * 8) * 2;
                ldsm_x4_t(bh[g2], sD + boff);
            }
#pragma unroll
            for (int g2 = 0; g2 < 4; g2++) {
                mma16816(acc2[2 * g2],     Ph[kt], bh[g2][0], bh[g2][1]);
                mma16816(acc2[2 * g2 + 1], Ph[kt], bh[g2][2], bh[g2][3]);
            }
#pragma unroll
            for (int g2 = 0; g2 < 4; g2++) {
                mma16816(acc2[2 * g2],     Pl[kt], bh[g2][0], bh[g2][1]);
                mma16816(acc2[2 * g2 + 1], Pl[kt], bh[g2][2], bh[g2][3]);
            }
        }
#pragma unroll
        for (int nt2 = 0; nt2 < 8; nt2++) {
            int gc = nc * 64 + nt2 * 8 + tr * 2;
            float2 b2 = *(const float2*)(dec_b + gc);
            float2 o0, o1;
            o0.x = acc2[nt2][0] + b2.x; o0.y = acc2[nt2][1] + b2.y;
            o1.x = acc2[nt2][2] + b2.x; o1.y = acc2[nt2][3] + b2.y;
            *(float2*)(recon + ra * DIN + gc)       = o0;
            *(float2*)(recon + (ra + 8) * DIN + gc) = o1;
        }
    }
}

// ---------------------------------------------------------------------------
extern "C" void kernel_launch(void* const* d_in, const int* in_sizes, int n_in,
                              void* d_out, int out_size)
{
    const float* seq   = (const float*)d_in[0];
    const float* enc_w = (const float*)d_in[1];
    const float* enc_b = (const float*)d_in[2];
    const float* mem   = (const float*)d_in[3];
    const float* dec_w = (const float*)d_in[4];
    const float* dec_b = (const float*)d_in[5];

    float* recon = (float*)d_out;
    float* att   = recon + (size_t)NTOK * DIN;
    float* memo  = att   + (size_t)NTOK * MS;

    cudaFuncSetAttribute(enc_gemm,
                         cudaFuncAttributeMaxDynamicSharedMemorySize, GEMM_SMEM);
    cudaFuncSetAttribute(attn_fused,
                         cudaFuncAttributeMaxDynamicSharedMemorySize, AT_SMEM);

    prep_cvt<<<160, 256>>>(enc_w, mem);
    prep_dt<<<DIN / 4, 256>>>(dec_w, mem);

    dim3 g1(DK / 128, NTOK / 128);
    enc_gemm<<<g1, 512, GEMM_SMEM>>>(seq, enc_b);

    attn_fused<<<NTOK / 256, 512, AT_SMEM>>>(att, memo, recon, dec_b);
}